// round 9
// baseline (speedup 1.0000x reference)
#include <cuda_runtime.h>
#include <cstdint>

#define N_NODES 50000
#define N_EDGES 160000
#define DIM     512
#define N_GRAPHS 64
#define EPSV    1e-5f

// GEMM: persistent, BM=128, BN=128, BK=32, 3-stage cp.async, 8 warps, warp 64x32, 2 CTAs/SM
#define AS_STR 36
#define BS_STR 136
#define AS_ELE (128 * AS_STR)
#define BS_ELE (32 * BS_STR)
#define NSTAGE 3
#define SMEM_BYTES (NSTAGE * (AS_ELE + BS_ELE) * 4)   // 107520 B
#define N_MTILE 391
#define N_NTILE 4
#define N_TILES (N_MTILE * N_NTILE)    // 1564
#define NCTA_GEMM 296                  // 2 per SM on 148 SMs

// scatter slicing
#define NSLICE 4
#define SLICE_F (DIM / NSLICE)
#define EDGES_PER_BLK 8

// ---- scratch (static __device__: allocation-free) ----
__device__ float g_xw [(size_t)N_NODES * DIM];
__device__ float g_acc[(size_t)N_NODES * DIM];
__device__ float g_deg[N_NODES];
__device__ float g_coef[N_EDGES];
__device__ float g_sum[N_GRAPHS * DIM];
__device__ float g_sq [N_GRAPHS * DIM];
__device__ float g_cnt[N_GRAPHS];
__device__ int   g_ei_row[N_EDGES];
__device__ int   g_ei_col[N_EDGES];
__device__ int   g_batch [N_NODES];

// ---------------------------------------------------------------- init
__global__ void k_init() {
    int i = blockIdx.x * blockDim.x + threadIdx.x;
    if (i < N_NODES) g_deg[i] = 1.0f;
    if (i < N_GRAPHS * DIM) { g_sum[i] = 0.f; g_sq[i] = 0.f; }
    if (i < N_GRAPHS) g_cnt[i] = 0.f;
}

// ---------------------------------------------------------------- dtype-robust index conversion + degree
__global__ void k_convert(const void* __restrict__ ei, const void* __restrict__ batch,
                          const float* __restrict__ w) {
    __shared__ int s64;
    const int tid = threadIdx.x;
    if (tid == 0) {
        const long long* q = (const long long*)ei;
        int ok = 1;
#pragma unroll
        for (int i = 0; i < 8; i++) { long long v = q[i]; if (v < 0 || v >= N_NODES) ok = 0; }
        s64 = ok;
    }
    __syncthreads();
    const int is64 = s64;
    const int e = blockIdx.x * blockDim.x + tid;
    if (e < N_EDGES) {
        int r, c;
        if (is64) { r = (int)((const long long*)ei)[e]; c = (int)((const long long*)ei)[N_EDGES + e]; }
        else      { r = ((const int*)ei)[e];            c = ((const int*)ei)[N_EDGES + e]; }
        r = min(max(r, 0), N_NODES - 1);
        c = min(max(c, 0), N_NODES - 1);
        g_ei_row[e] = r;
        g_ei_col[e] = c;
        atomicAdd(&g_deg[c], w[e]);
    }
    if (e < N_NODES) {
        int bv = is64 ? (int)((const long long*)batch)[e] : ((const int*)batch)[e];
        g_batch[e] = min(max(bv, 0), N_GRAPHS - 1);
    }
}

// ---------------------------------------------------------------- helpers
__device__ __forceinline__ void cpasync16(uint32_t dst, const void* src) {
    asm volatile("cp.async.cg.shared.global [%0], [%1], 16;" :: "r"(dst), "l"(src));
}
#define CP_COMMIT()  asm volatile("cp.async.commit_group;" ::: "memory")
#define CP_WAIT(n)   asm volatile("cp.async.wait_group %0;" :: "n"(n) : "memory")
__device__ __forceinline__ uint32_t smem_u32(const void* p) {
    uint32_t a;
    asm("{ .reg .u64 t; cvta.to.shared.u64 t, %1; cvt.u32.u64 %0, t; }" : "=r"(a) : "l"(p));
    return a;
}
__device__ __forceinline__ void mma_tf32(float* d, const uint32_t* a, const uint32_t* b) {
    asm volatile(
        "mma.sync.aligned.m16n8k8.row.col.f32.tf32.tf32.f32 "
        "{%0,%1,%2,%3},{%4,%5,%6,%7},{%8,%9},{%0,%1,%2,%3};\n"
        : "+f"(d[0]), "+f"(d[1]), "+f"(d[2]), "+f"(d[3])
        : "r"(a[0]), "r"(a[1]), "r"(a[2]), "r"(a[3]), "r"(b[0]), "r"(b[1]));
}

// ---------------------------------------------------------------- persistent GEMM + fused epilogue
// C = node @ W, tf32 mma.sync.  296 CTAs x 256 threads, each loops ~5.3 tiles.
// Chunk pipeline runs continuously across tile boundaries (stage bufs mod 3),
// so next tile's loads overlap this tile's tail + epilogue.
__global__ void __launch_bounds__(256, 2) k_gemm(
    const float* __restrict__ A,
    const float* __restrict__ B,
    const float* __restrict__ bias)
{
    extern __shared__ float smem[];
    const uint32_t sbase = smem_u32(smem);
    const int tid  = threadIdx.x;
    const int lane = tid & 31;
    const int warp = tid >> 5;
    const int wm = warp >> 2;   // 0..1
    const int wn = warp & 3;    // 0..3
    const int cta = blockIdx.x;
    const int ntiles = (N_TILES - cta + NCTA_GEMM - 1) / NCTA_GEMM;

    // issue chunk g (16 chunks per tile); empty commit beyond range keeps groups aligned
#define ISSUE(G) do {                                                            \
        const int g_ = (G);                                                      \
        const int tile_ = cta + (g_ >> 4) * NCTA_GEMM;                           \
        if (tile_ < N_TILES) {                                                   \
            const int kk = (g_ & 15) * 32;                                       \
            const int gm0_ = (tile_ >> 2) * 128;                                 \
            const int gn0_ = (tile_ & 3) * 128;                                  \
            const int bf_ = g_ % NSTAGE;                                         \
            const uint32_t sa = sbase + bf_ * (AS_ELE * 4);                      \
            const uint32_t sbb = sbase + (NSTAGE * AS_ELE + bf_ * BS_ELE) * 4;   \
            _Pragma("unroll")                                                    \
            for (int i = 0; i < 4; i++) {                                        \
                const int idx = tid + i * 256;                                   \
                const int row = idx >> 3, col = (idx & 7) * 4;                   \
                int gm = gm0_ + row;                                             \
                if (gm >= N_NODES) gm = N_NODES - 1;                             \
                cpasync16(sa + (uint32_t)(row * AS_STR + col) * 4,               \
                          A + (size_t)gm * 512 + kk + col);                      \
            }                                                                    \
            _Pragma("unroll")                                                    \
            for (int i = 0; i < 4; i++) {                                        \
                const int idx = tid + i * 256;                                   \
                const int row = idx >> 5, col = (idx & 31) * 4;                  \
                cpasync16(sbb + (uint32_t)(row * BS_STR + col) * 4,              \
                          B + (size_t)(kk + row) * 512 + gn0_ + col);            \
            }                                                                    \
        }                                                                        \
        CP_COMMIT();                                                             \
    } while (0)

    ISSUE(0);
    ISSUE(1);

    int g = 0;
#pragma unroll 1
    for (int tl = 0; tl < ntiles; tl++) {
        const int tile = cta + tl * NCTA_GEMM;
        const int m0 = (tile >> 2) * 128;
        const int n0 = (tile & 3) * 128;

        float acc[4][4][4];
#pragma unroll
        for (int i = 0; i < 4; i++)
#pragma unroll
            for (int j = 0; j < 4; j++)
#pragma unroll
                for (int c = 0; c < 4; c++) acc[i][j][c] = 0.f;

#pragma unroll 1
        for (int kt = 0; kt < 16; kt++, g++) {
            CP_WAIT(1);
            __syncthreads();
            ISSUE(g + 2);

            const int buf = g % NSTAGE;
            const float* as = smem + buf * AS_ELE;
            const float* bs = smem + NSTAGE * AS_ELE + buf * BS_ELE;
#pragma unroll
            for (int ks = 0; ks < 4; ks++) {
                uint32_t af[4][4], bf[4][2];
                const int kk = ks * 8 + (lane & 3);
#pragma unroll
                for (int i = 0; i < 4; i++) {
                    const int r = wm * 64 + i * 16 + (lane >> 2);
                    af[i][0] = __float_as_uint(as[r * AS_STR + kk]);
                    af[i][1] = __float_as_uint(as[(r + 8) * AS_STR + kk]);
                    af[i][2] = __float_as_uint(as[r * AS_STR + kk + 4]);
                    af[i][3] = __float_as_uint(as[(r + 8) * AS_STR + kk + 4]);
                }
#pragma unroll
                for (int j = 0; j < 4; j++) {
                    const int c = wn * 32 + j * 8 + (lane >> 2);
                    bf[j][0] = __float_as_uint(bs[kk * BS_STR + c]);
                    bf[j][1] = __float_as_uint(bs[(kk + 4) * BS_STR + c]);
                }
#pragma unroll
                for (int i = 0; i < 4; i++)
#pragma unroll
                    for (int j = 0; j < 4; j++)
                        mma_tf32(acc[i][j], af[i], bf[j]);
            }
        }

        // epilogue (no smem use -> overlaps next tile's prefetched pipeline)
#pragma unroll
        for (int i = 0; i < 4; i++) {
            const int rbase = m0 + wm * 64 + i * 16 + (lane >> 2);
#pragma unroll
            for (int h = 0; h < 2; h++) {
                const int gm = rbase + h * 8;
                if (gm < N_NODES) {
                    const float invdeg = 1.0f / g_deg[gm];
#pragma unroll
                    for (int j = 0; j < 4; j++) {
                        const int cb = n0 + wn * 32 + j * 8 + ((lane & 3) << 1);
                        const size_t o = (size_t)gm * 512 + cb;
                        const float v0 = acc[i][j][h * 2 + 0];
                        const float v1 = acc[i][j][h * 2 + 1];
                        *(float2*)(g_xw + o) = make_float2(v0, v1);
                        const float2 a2 = *(const float2*)(A + o);
                        const float2 b2 = *(const float2*)(bias + cb);
                        *(float2*)(g_acc + o) = make_float2(a2.x + b2.x + v0 * invdeg,
                                                            a2.y + b2.y + v1 * invdeg);
                    }
                }
            }
        }
    }
#undef ISSUE
}

// ---------------------------------------------------------------- edge scatter (feature-sliced)
// slice 0 computes + stores per-edge coef; slices 1..3 reuse it.
__global__ __launch_bounds__(256) void k_scatter(const float* __restrict__ w, int slice) {
    const int e = blockIdx.x * EDGES_PER_BLK + (threadIdx.x >> 5);
    if (e >= N_EDGES) return;
    const int t = threadIdx.x & 31;
    const int r = g_ei_row[e];
    const int c = g_ei_col[e];
    float coef;
    if (slice == 0) {
        coef = w[e] * rsqrtf(g_deg[r]) * rsqrtf(g_deg[c]);
        if (t == 0) g_coef[e] = coef;
    } else {
        coef = g_coef[e];
    }
    const float4* src = (const float4*)(g_xw + (size_t)r * DIM + slice * SLICE_F);
    float4* dst = (float4*)(g_acc + (size_t)c * DIM + slice * SLICE_F);
    const float4 v = src[t];
    asm volatile("red.global.add.v4.f32 [%0], {%1,%2,%3,%4};"
                 :: "l"(dst + t), "f"(v.x * coef), "f"(v.y * coef),
                    "f"(v.z * coef), "f"(v.w * coef)
                 : "memory");
}

// ---------------------------------------------------------------- GraphNorm stats (single pass)
__global__ __launch_bounds__(256) void k_stats() {
    const int n0 = blockIdx.x * 128;
    const int nend = min(n0 + 128, N_NODES);
    const int t = threadIdx.x;
    const int d0 = t, d1 = t + 256;
    float s0 = 0.f, s1 = 0.f, q0 = 0.f, q1 = 0.f;
    int g = g_batch[n0], cnt = 0;
    for (int n = n0; n < nend; n++) {
        const int gn = g_batch[n];
        if (gn != g) {
            atomicAdd(&g_sum[g * DIM + d0], s0);
            atomicAdd(&g_sum[g * DIM + d1], s1);
            atomicAdd(&g_sq [g * DIM + d0], q0);
            atomicAdd(&g_sq [g * DIM + d1], q1);
            if (t == 0) atomicAdd(&g_cnt[g], (float)cnt);
            s0 = s1 = q0 = q1 = 0.f; cnt = 0; g = gn;
        }
        const float* row = g_acc + (size_t)n * DIM;
        const float x0 = row[d0], x1 = row[d1];
        s0 += x0; s1 += x1; q0 += x0 * x0; q1 += x1 * x1; cnt++;
    }
    atomicAdd(&g_sum[g * DIM + d0], s0);
    atomicAdd(&g_sum[g * DIM + d1], s1);
    atomicAdd(&g_sq [g * DIM + d0], q0);
    atomicAdd(&g_sq [g * DIM + d1], q1);
    if (t == 0) atomicAdd(&g_cnt[g], (float)cnt);
}

// ---------------------------------------------------------------- finalize: normalize + relu
__global__ __launch_bounds__(256) void k_final(const float* __restrict__ gw,
                                               const float* __restrict__ gb,
                                               const float* __restrict__ ms,
                                               float* __restrict__ out) {
    const int idx = blockIdx.x * blockDim.x + threadIdx.x;
    if (idx >= N_NODES * (DIM / 4)) return;
    const int n = idx >> 7;
    const int dc = (idx & 127) << 2;
    const int g = g_batch[n];
    const float ic = 1.f / fmaxf(g_cnt[g], 1.f);
    const float4 x  = *(const float4*)(g_acc + (size_t)n * DIM + dc);
    const float4 sm = *(const float4*)(g_sum + g * DIM + dc);
    const float4 sq = *(const float4*)(g_sq  + g * DIM + dc);
    const float4 w4 = *(const float4*)(gw + dc);
    const float4 b4 = *(const float4*)(gb + dc);
    const float4 m4 = *(const float4*)(ms + dc);
    float4 o;
    {
        const float m = sm.x * ic, c = m * m4.x;
        const float var = sq.x * ic - 2.f * c * m + c * c;
        o.x = fmaxf(w4.x * (x.x - c) * rsqrtf(var + EPSV) + b4.x, 0.f);
    }
    {
        const float m = sm.y * ic, c = m * m4.y;
        const float var = sq.y * ic - 2.f * c * m + c * c;
        o.y = fmaxf(w4.y * (x.y - c) * rsqrtf(var + EPSV) + b4.y, 0.f);
    }
    {
        const float m = sm.z * ic, c = m * m4.z;
        const float var = sq.z * ic - 2.f * c * m + c * c;
        o.z = fmaxf(w4.z * (x.z - c) * rsqrtf(var + EPSV) + b4.z, 0.f);
    }
    {
        const float m = sm.w * ic, c = m * m4.w;
        const float var = sq.w * ic - 2.f * c * m + c * c;
        o.w = fmaxf(w4.w * (x.w - c) * rsqrtf(var + EPSV) + b4.w, 0.f);
    }
    *(float4*)(out + (size_t)n * DIM + dc) = o;
}

// ---------------------------------------------------------------- launch
extern "C" void kernel_launch(void* const* d_in, const int* in_sizes, int n_in,
                              void* d_out, int out_size) {
    const float* node  = (const float*)d_in[0];
    const float* eattr = (const float*)d_in[1];
    const float* W     = (const float*)d_in[2];
    const float* b     = (const float*)d_in[3];
    const float* gw    = (const float*)d_in[4];
    const float* gb    = (const float*)d_in[5];
    const float* ms    = (const float*)d_in[6];
    const void*  ei    = d_in[7];
    const void*  batch = d_in[8];
    float* out = (float*)d_out;

    cudaFuncSetAttribute(k_gemm, cudaFuncAttributeMaxDynamicSharedMemorySize, SMEM_BYTES);

    k_init<<<(N_NODES + 255) / 256, 256>>>();
    k_convert<<<(N_EDGES + 255) / 256, 256>>>(ei, batch, eattr);
    k_gemm<<<NCTA_GEMM, 256, SMEM_BYTES>>>(node, W, b);
    {
        const int blocks = (N_EDGES + EDGES_PER_BLK - 1) / EDGES_PER_BLK;
        for (int s = 0; s < NSLICE; s++)
            k_scatter<<<blocks, 256>>>(eattr, s);
    }
    k_stats<<<(N_NODES + 127) / 128, 256>>>();
    k_final<<<(N_NODES * (DIM / 4) + 255) / 256, 256>>>(gw, gb, ms, out);
}

// round 10
// speedup vs baseline: 1.0706x; 1.0706x over previous
#include <cuda_runtime.h>
#include <cstdint>

#define N_NODES 50000
#define N_EDGES 160000
#define DIM     512
#define N_GRAPHS 64
#define EPSV    1e-5f

// GEMM tiling: BM=128, BN=128, BK=32, 3-stage cp.async, 8 warps, warp tile 64x32, 2 CTAs/SM
#define AS_STR 36
#define BS_STR 136
#define AS_ELE (128 * AS_STR)
#define BS_ELE (32 * BS_STR)
#define NSTAGE 3
#define SMEM_BYTES (NSTAGE * (AS_ELE + BS_ELE) * 4)   // 107520 B

// scatter: 4 feature slices of 128 floats; one warp handles 8 edges per slice
#define NSLICE 4
#define SLICE_F (DIM / NSLICE)
#define EDGES_PER_WARP 8
#define WARPS_PER_BLK 8
#define EDGES_PER_BLK (EDGES_PER_WARP * WARPS_PER_BLK)   // 64

// ---- scratch (static __device__: allocation-free) ----
__device__ float g_xw [(size_t)N_NODES * DIM];
__device__ float g_acc[(size_t)N_NODES * DIM];
__device__ float g_deg[N_NODES];
__device__ float g_coef[N_EDGES];
__device__ float g_sum[N_GRAPHS * DIM];
__device__ float g_sq [N_GRAPHS * DIM];
__device__ float g_cnt[N_GRAPHS];
__device__ int   g_ei_row[N_EDGES];
__device__ int   g_ei_col[N_EDGES];
__device__ int   g_batch [N_NODES];

// ---------------------------------------------------------------- init
__global__ void k_init() {
    int i = blockIdx.x * blockDim.x + threadIdx.x;
    if (i < N_NODES) g_deg[i] = 1.0f;
    if (i < N_GRAPHS * DIM) { g_sum[i] = 0.f; g_sq[i] = 0.f; }
    if (i < N_GRAPHS) g_cnt[i] = 0.f;
}

// ---------------------------------------------------------------- dtype-robust index conversion + degree
__global__ void k_convert(const void* __restrict__ ei, const void* __restrict__ batch,
                          const float* __restrict__ w) {
    __shared__ int s64;
    const int tid = threadIdx.x;
    if (tid == 0) {
        const long long* q = (const long long*)ei;
        int ok = 1;
#pragma unroll
        for (int i = 0; i < 8; i++) { long long v = q[i]; if (v < 0 || v >= N_NODES) ok = 0; }
        s64 = ok;
    }
    __syncthreads();
    const int is64 = s64;
    const int e = blockIdx.x * blockDim.x + tid;
    if (e < N_EDGES) {
        int r, c;
        if (is64) { r = (int)((const long long*)ei)[e]; c = (int)((const long long*)ei)[N_EDGES + e]; }
        else      { r = ((const int*)ei)[e];            c = ((const int*)ei)[N_EDGES + e]; }
        r = min(max(r, 0), N_NODES - 1);
        c = min(max(c, 0), N_NODES - 1);
        g_ei_row[e] = r;
        g_ei_col[e] = c;
        atomicAdd(&g_deg[c], w[e]);
    }
    if (e < N_NODES) {
        int bv = is64 ? (int)((const long long*)batch)[e] : ((const int*)batch)[e];
        g_batch[e] = min(max(bv, 0), N_GRAPHS - 1);
    }
}

// ---------------------------------------------------------------- helpers
__device__ __forceinline__ void cpasync16(uint32_t dst, const void* src) {
    asm volatile("cp.async.cg.shared.global [%0], [%1], 16;" :: "r"(dst), "l"(src));
}
#define CP_COMMIT()  asm volatile("cp.async.commit_group;" ::: "memory")
#define CP_WAIT(n)   asm volatile("cp.async.wait_group %0;" :: "n"(n) : "memory")
__device__ __forceinline__ uint32_t smem_u32(const void* p) {
    uint32_t a;
    asm("{ .reg .u64 t; cvta.to.shared.u64 t, %1; cvt.u32.u64 %0, t; }" : "=r"(a) : "l"(p));
    return a;
}
__device__ __forceinline__ void mma_tf32(float* d, const uint32_t* a, const uint32_t* b) {
    asm volatile(
        "mma.sync.aligned.m16n8k8.row.col.f32.tf32.tf32.f32 "
        "{%0,%1,%2,%3},{%4,%5,%6,%7},{%8,%9},{%0,%1,%2,%3};\n"
        : "+f"(d[0]), "+f"(d[1]), "+f"(d[2]), "+f"(d[3])
        : "r"(a[0]), "r"(a[1]), "r"(a[2]), "r"(a[3]), "r"(b[0]), "r"(b[1]));
}

// ---------------------------------------------------------------- GEMM + fused epilogue (R8 version)
__global__ void __launch_bounds__(256, 2) k_gemm(
    const float* __restrict__ A,
    const float* __restrict__ B,
    const float* __restrict__ bias)
{
    extern __shared__ float smem[];
    const uint32_t sbase = smem_u32(smem);
    const int tid  = threadIdx.x;
    const int lane = tid & 31;
    const int warp = tid >> 5;
    const int wm = warp >> 2;   // 0..1
    const int wn = warp & 3;    // 0..3
    const int m0 = blockIdx.y * 128;
    const int n0 = blockIdx.x * 128;

    float acc[4][4][4];
#pragma unroll
    for (int i = 0; i < 4; i++)
#pragma unroll
        for (int j = 0; j < 4; j++)
#pragma unroll
            for (int c = 0; c < 4; c++) acc[i][j][c] = 0.f;

#define ISSUE(KT) do {                                                           \
        const int kk = (KT) * 32;                                                \
        const uint32_t sa = sbase + ((KT) % NSTAGE) * (AS_ELE * 4);              \
        const uint32_t sbb = sbase + (NSTAGE * AS_ELE + ((KT) % NSTAGE) * BS_ELE) * 4; \
        _Pragma("unroll")                                                        \
        for (int i = 0; i < 4; i++) {                                            \
            const int idx = tid + i * 256;                                       \
            const int row = idx >> 3, col = (idx & 7) * 4;                       \
            int gm = m0 + row;                                                   \
            if (gm >= N_NODES) gm = N_NODES - 1;                                 \
            cpasync16(sa + (uint32_t)(row * AS_STR + col) * 4,                   \
                      A + (size_t)gm * 512 + kk + col);                          \
        }                                                                        \
        _Pragma("unroll")                                                        \
        for (int i = 0; i < 4; i++) {                                            \
            const int idx = tid + i * 256;                                       \
            const int row = idx >> 5, col = (idx & 31) * 4;                      \
            cpasync16(sbb + (uint32_t)(row * BS_STR + col) * 4,                  \
                      B + (size_t)(kk + row) * 512 + n0 + col);                  \
        }                                                                        \
        CP_COMMIT();                                                             \
    } while (0)

    ISSUE(0);
    ISSUE(1);

#pragma unroll 1
    for (int kt = 0; kt < 16; kt++) {
        CP_WAIT(1);
        __syncthreads();
        if (kt + 2 < 16) ISSUE(kt + 2);

        const float* as = smem + (kt % NSTAGE) * AS_ELE;
        const float* bs = smem + NSTAGE * AS_ELE + (kt % NSTAGE) * BS_ELE;
#pragma unroll
        for (int ks = 0; ks < 4; ks++) {
            uint32_t af[4][4], bf[4][2];
            const int kk = ks * 8 + (lane & 3);
#pragma unroll
            for (int i = 0; i < 4; i++) {
                const int r = wm * 64 + i * 16 + (lane >> 2);
                af[i][0] = __float_as_uint(as[r * AS_STR + kk]);
                af[i][1] = __float_as_uint(as[(r + 8) * AS_STR + kk]);
                af[i][2] = __float_as_uint(as[r * AS_STR + kk + 4]);
                af[i][3] = __float_as_uint(as[(r + 8) * AS_STR + kk + 4]);
            }
#pragma unroll
            for (int j = 0; j < 4; j++) {
                const int c = wn * 32 + j * 8 + (lane >> 2);
                bf[j][0] = __float_as_uint(bs[kk * BS_STR + c]);
                bf[j][1] = __float_as_uint(bs[(kk + 4) * BS_STR + c]);
            }
#pragma unroll
            for (int i = 0; i < 4; i++)
#pragma unroll
                for (int j = 0; j < 4; j++)
                    mma_tf32(acc[i][j], af[i], bf[j]);
        }
    }

    // epilogue
#pragma unroll
    for (int i = 0; i < 4; i++) {
        const int rbase = m0 + wm * 64 + i * 16 + (lane >> 2);
#pragma unroll
        for (int h = 0; h < 2; h++) {
            const int gm = rbase + h * 8;
            if (gm < N_NODES) {
                const float invdeg = 1.0f / g_deg[gm];
#pragma unroll
                for (int j = 0; j < 4; j++) {
                    const int cb = n0 + wn * 32 + j * 8 + ((lane & 3) << 1);
                    const size_t o = (size_t)gm * 512 + cb;
                    const float v0 = acc[i][j][h * 2 + 0];
                    const float v1 = acc[i][j][h * 2 + 1];
                    *(float2*)(g_xw + o) = make_float2(v0, v1);
                    const float2 a2 = *(const float2*)(A + o);
                    const float2 b2 = *(const float2*)(bias + cb);
                    *(float2*)(g_acc + o) = make_float2(a2.x + b2.x + v0 * invdeg,
                                                        a2.y + b2.y + v1 * invdeg);
                }
            }
        }
    }
#undef ISSUE
}

// ---------------------------------------------------------------- edge scatter (sliced, 8 edges/warp)
// Slicing keeps the per-launch working set (~25MB src + 25MB dst) L2-resident;
// 8 independent edges per warp restore MLP (8 outstanding 512B gathers/lane).
// Slice 0 also computes + stores the per-edge coefficient.
__global__ void __launch_bounds__(256) k_scatter(const float* __restrict__ w, int slice) {
    const int wid = blockIdx.x * WARPS_PER_BLK + (threadIdx.x >> 5);
    const int t = threadIdx.x & 31;
    const int e0 = wid * EDGES_PER_WARP;

    int rr[EDGES_PER_WARP], cc[EDGES_PER_WARP];
    float cf[EDGES_PER_WARP];
#pragma unroll
    for (int i = 0; i < EDGES_PER_WARP; i++) {
        const int e = e0 + i;
        rr[i] = g_ei_row[e];
        cc[i] = g_ei_col[e];
    }
    if (slice == 0) {
#pragma unroll
        for (int i = 0; i < EDGES_PER_WARP; i++) {
            const int e = e0 + i;
            cf[i] = w[e] * rsqrtf(g_deg[rr[i]]) * rsqrtf(g_deg[cc[i]]);
            if (t == 0) g_coef[e] = cf[i];
        }
    } else {
#pragma unroll
        for (int i = 0; i < EDGES_PER_WARP; i++) cf[i] = g_coef[e0 + i];
    }

    const int fo = slice * SLICE_F + t * 4;
    float4 v[EDGES_PER_WARP];
#pragma unroll
    for (int i = 0; i < EDGES_PER_WARP; i++)
        v[i] = *(const float4*)(g_xw + (size_t)rr[i] * DIM + fo);
#pragma unroll
    for (int i = 0; i < EDGES_PER_WARP; i++) {
        float4* dst = (float4*)(g_acc + (size_t)cc[i] * DIM + fo);
        asm volatile("red.global.add.v4.f32 [%0], {%1,%2,%3,%4};"
                     :: "l"(dst), "f"(v[i].x * cf[i]), "f"(v[i].y * cf[i]),
                        "f"(v[i].z * cf[i]), "f"(v[i].w * cf[i])
                     : "memory");
    }
}

// ---------------------------------------------------------------- GraphNorm stats (single pass)
__global__ __launch_bounds__(256) void k_stats() {
    const int n0 = blockIdx.x * 128;
    const int nend = min(n0 + 128, N_NODES);
    const int t = threadIdx.x;
    const int d0 = t, d1 = t + 256;
    float s0 = 0.f, s1 = 0.f, q0 = 0.f, q1 = 0.f;
    int g = g_batch[n0], cnt = 0;
    for (int n = n0; n < nend; n++) {
        const int gn = g_batch[n];
        if (gn != g) {
            atomicAdd(&g_sum[g * DIM + d0], s0);
            atomicAdd(&g_sum[g * DIM + d1], s1);
            atomicAdd(&g_sq [g * DIM + d0], q0);
            atomicAdd(&g_sq [g * DIM + d1], q1);
            if (t == 0) atomicAdd(&g_cnt[g], (float)cnt);
            s0 = s1 = q0 = q1 = 0.f; cnt = 0; g = gn;
        }
        const float* row = g_acc + (size_t)n * DIM;
        const float x0 = row[d0], x1 = row[d1];
        s0 += x0; s1 += x1; q0 += x0 * x0; q1 += x1 * x1; cnt++;
    }
    atomicAdd(&g_sum[g * DIM + d0], s0);
    atomicAdd(&g_sum[g * DIM + d1], s1);
    atomicAdd(&g_sq [g * DIM + d0], q0);
    atomicAdd(&g_sq [g * DIM + d1], q1);
    if (t == 0) atomicAdd(&g_cnt[g], (float)cnt);
}

// ---------------------------------------------------------------- finalize: normalize + relu
__global__ __launch_bounds__(256) void k_final(const float* __restrict__ gw,
                                               const float* __restrict__ gb,
                                               const float* __restrict__ ms,
                                               float* __restrict__ out) {
    const int idx = blockIdx.x * blockDim.x + threadIdx.x;
    if (idx >= N_NODES * (DIM / 4)) return;
    const int n = idx >> 7;
    const int dc = (idx & 127) << 2;
    const int g = g_batch[n];
    const float ic = 1.f / fmaxf(g_cnt[g], 1.f);
    const float4 x  = *(const float4*)(g_acc + (size_t)n * DIM + dc);
    const float4 sm = *(const float4*)(g_sum + g * DIM + dc);
    const float4 sq = *(const float4*)(g_sq  + g * DIM + dc);
    const float4 w4 = *(const float4*)(gw + dc);
    const float4 b4 = *(const float4*)(gb + dc);
    const float4 m4 = *(const float4*)(ms + dc);
    float4 o;
    {
        const float m = sm.x * ic, c = m * m4.x;
        const float var = sq.x * ic - 2.f * c * m + c * c;
        o.x = fmaxf(w4.x * (x.x - c) * rsqrtf(var + EPSV) + b4.x, 0.f);
    }
    {
        const float m = sm.y * ic, c = m * m4.y;
        const float var = sq.y * ic - 2.f * c * m + c * c;
        o.y = fmaxf(w4.y * (x.y - c) * rsqrtf(var + EPSV) + b4.y, 0.f);
    }
    {
        const float m = sm.z * ic, c = m * m4.z;
        const float var = sq.z * ic - 2.f * c * m + c * c;
        o.z = fmaxf(w4.z * (x.z - c) * rsqrtf(var + EPSV) + b4.z, 0.f);
    }
    {
        const float m = sm.w * ic, c = m * m4.w;
        const float var = sq.w * ic - 2.f * c * m + c * c;
        o.w = fmaxf(w4.w * (x.w - c) * rsqrtf(var + EPSV) + b4.w, 0.f);
    }
    *(float4*)(out + (size_t)n * DIM + dc) = o;
}

// ---------------------------------------------------------------- launch
extern "C" void kernel_launch(void* const* d_in, const int* in_sizes, int n_in,
                              void* d_out, int out_size) {
    const float* node  = (const float*)d_in[0];
    const float* eattr = (const float*)d_in[1];
    const float* W     = (const float*)d_in[2];
    const float* b     = (const float*)d_in[3];
    const float* gw    = (const float*)d_in[4];
    const float* gb    = (const float*)d_in[5];
    const float* ms    = (const float*)d_in[6];
    const void*  ei    = d_in[7];
    const void*  batch = d_in[8];
    float* out = (float*)d_out;

    cudaFuncSetAttribute(k_gemm, cudaFuncAttributeMaxDynamicSharedMemorySize, SMEM_BYTES);

    k_init<<<(N_NODES + 255) / 256, 256>>>();
    k_convert<<<(N_EDGES + 255) / 256, 256>>>(ei, batch, eattr);
    {
        dim3 grid(DIM / 128, (N_NODES + 127) / 128);   // (4, 391)
        k_gemm<<<grid, 256, SMEM_BYTES>>>(node, W, b);
    }
    {
        const int blocks = N_EDGES / EDGES_PER_BLK;    // 2500
        for (int s = 0; s < NSLICE; s++)
            k_scatter<<<blocks, 256>>>(eattr, s);
    }
    k_stats<<<(N_NODES + 127) / 128, 256>>>();
    k_final<<<(N_NODES * (DIM / 4) + 255) / 256, 256>>>(gw, gb, ms, out);
}

// round 11
// speedup vs baseline: 1.0937x; 1.0216x over previous
#include <cuda_runtime.h>
#include <cstdint>

#define N_NODES 50000
#define N_EDGES 160000
#define DIM     512
#define N_GRAPHS 64
#define EPSV    1e-5f

// GEMM tiling: BM=128, BN=128, BK=32, 3-stage cp.async, 8 warps, warp tile 64x32, 2 CTAs/SM
#define AS_STR 36
#define BS_STR 136
#define AS_ELE (128 * AS_STR)
#define BS_ELE (32 * BS_STR)
#define NSTAGE 3
#define SMEM_BYTES (NSTAGE * (AS_ELE + BS_ELE) * 4)   // 107520 B

// gather: padded CSR (32 slots/dst), 4 feature slices of 128 floats, 1 warp/dst
#define SLOTS 32
#define NSLICE 4
#define SLICE_F (DIM / NSLICE)
#define WPB 8

// ---- scratch (static __device__: allocation-free) ----
__device__ float g_xw [(size_t)N_NODES * DIM];
__device__ float g_acc[(size_t)N_NODES * DIM];
__device__ float g_deg[N_NODES];
__device__ int   g_slot[N_NODES];                    // in-degree counter / CSR count
__device__ int   g_csr_src[(size_t)N_NODES * SLOTS];
__device__ float g_csr_cf [(size_t)N_NODES * SLOTS];
__device__ float g_sum[N_GRAPHS * DIM];
__device__ float g_sq [N_GRAPHS * DIM];
__device__ float g_cnt[N_GRAPHS];
__device__ int   g_ei_row[N_EDGES];
__device__ int   g_ei_col[N_EDGES];
__device__ int   g_batch [N_NODES];

// ---------------------------------------------------------------- init
__global__ void k_init() {
    int i = blockIdx.x * blockDim.x + threadIdx.x;
    if (i < N_NODES) { g_deg[i] = 1.0f; g_slot[i] = 0; }
    if (i < N_GRAPHS * DIM) { g_sum[i] = 0.f; g_sq[i] = 0.f; }
    if (i < N_GRAPHS) g_cnt[i] = 0.f;
}

// ---------------------------------------------------------------- dtype-robust index conversion + degree
__global__ void k_convert(const void* __restrict__ ei, const void* __restrict__ batch,
                          const float* __restrict__ w) {
    __shared__ int s64;
    const int tid = threadIdx.x;
    if (tid == 0) {
        const long long* q = (const long long*)ei;
        int ok = 1;
#pragma unroll
        for (int i = 0; i < 8; i++) { long long v = q[i]; if (v < 0 || v >= N_NODES) ok = 0; }
        s64 = ok;
    }
    __syncthreads();
    const int is64 = s64;
    const int e = blockIdx.x * blockDim.x + tid;
    if (e < N_EDGES) {
        int r, c;
        if (is64) { r = (int)((const long long*)ei)[e]; c = (int)((const long long*)ei)[N_EDGES + e]; }
        else      { r = ((const int*)ei)[e];            c = ((const int*)ei)[N_EDGES + e]; }
        r = min(max(r, 0), N_NODES - 1);
        c = min(max(c, 0), N_NODES - 1);
        g_ei_row[e] = r;
        g_ei_col[e] = c;
        atomicAdd(&g_deg[c], w[e]);
    }
    if (e < N_NODES) {
        int bv = is64 ? (int)((const long long*)batch)[e] : ((const int*)batch)[e];
        g_batch[e] = min(max(bv, 0), N_GRAPHS - 1);
    }
}

// ---------------------------------------------------------------- CSR fill (after deg final)
__global__ void k_fill(const float* __restrict__ w) {
    const int e = blockIdx.x * blockDim.x + threadIdx.x;
    if (e >= N_EDGES) return;
    const int r = g_ei_row[e];
    const int c = g_ei_col[e];
    const float coef = w[e] * rsqrtf(g_deg[r]) * rsqrtf(g_deg[c]);
    const int slot = atomicAdd(&g_slot[c], 1);
    if (slot < SLOTS) {
        g_csr_src[(size_t)c * SLOTS + slot] = r;
        g_csr_cf [(size_t)c * SLOTS + slot] = coef;
    }
}

// ---------------------------------------------------------------- helpers
__device__ __forceinline__ void cpasync16(uint32_t dst, const void* src) {
    asm volatile("cp.async.cg.shared.global [%0], [%1], 16;" :: "r"(dst), "l"(src));
}
#define CP_COMMIT()  asm volatile("cp.async.commit_group;" ::: "memory")
#define CP_WAIT(n)   asm volatile("cp.async.wait_group %0;" :: "n"(n) : "memory")
__device__ __forceinline__ uint32_t smem_u32(const void* p) {
    uint32_t a;
    asm("{ .reg .u64 t; cvta.to.shared.u64 t, %1; cvt.u32.u64 %0, t; }" : "=r"(a) : "l"(p));
    return a;
}
__device__ __forceinline__ void mma_tf32(float* d, const uint32_t* a, const uint32_t* b) {
    asm volatile(
        "mma.sync.aligned.m16n8k8.row.col.f32.tf32.tf32.f32 "
        "{%0,%1,%2,%3},{%4,%5,%6,%7},{%8,%9},{%0,%1,%2,%3};\n"
        : "+f"(d[0]), "+f"(d[1]), "+f"(d[2]), "+f"(d[3])
        : "r"(a[0]), "r"(a[1]), "r"(a[2]), "r"(a[3]), "r"(b[0]), "r"(b[1]));
}

// ---------------------------------------------------------------- GEMM + fused epilogue (R8 version)
__global__ void __launch_bounds__(256, 2) k_gemm(
    const float* __restrict__ A,
    const float* __restrict__ B,
    const float* __restrict__ bias)
{
    extern __shared__ float smem[];
    const uint32_t sbase = smem_u32(smem);
    const int tid  = threadIdx.x;
    const int lane = tid & 31;
    const int warp = tid >> 5;
    const int wm = warp >> 2;   // 0..1
    const int wn = warp & 3;    // 0..3
    const int m0 = blockIdx.y * 128;
    const int n0 = blockIdx.x * 128;

    float acc[4][4][4];
#pragma unroll
    for (int i = 0; i < 4; i++)
#pragma unroll
        for (int j = 0; j < 4; j++)
#pragma unroll
            for (int c = 0; c < 4; c++) acc[i][j][c] = 0.f;

#define ISSUE(KT) do {                                                           \
        const int kk = (KT) * 32;                                                \
        const uint32_t sa = sbase + ((KT) % NSTAGE) * (AS_ELE * 4);              \
        const uint32_t sbb = sbase + (NSTAGE * AS_ELE + ((KT) % NSTAGE) * BS_ELE) * 4; \
        _Pragma("unroll")                                                        \
        for (int i = 0; i < 4; i++) {                                            \
            const int idx = tid + i * 256;                                       \
            const int row = idx >> 3, col = (idx & 7) * 4;                       \
            int gm = m0 + row;                                                   \
            if (gm >= N_NODES) gm = N_NODES - 1;                                 \
            cpasync16(sa + (uint32_t)(row * AS_STR + col) * 4,                   \
                      A + (size_t)gm * 512 + kk + col);                          \
        }                                                                        \
        _Pragma("unroll")                                                        \
        for (int i = 0; i < 4; i++) {                                            \
            const int idx = tid + i * 256;                                       \
            const int row = idx >> 5, col = (idx & 31) * 4;                      \
            cpasync16(sbb + (uint32_t)(row * BS_STR + col) * 4,                  \
                      B + (size_t)(kk + row) * 512 + n0 + col);                  \
        }                                                                        \
        CP_COMMIT();                                                             \
    } while (0)

    ISSUE(0);
    ISSUE(1);

#pragma unroll 1
    for (int kt = 0; kt < 16; kt++) {
        CP_WAIT(1);
        __syncthreads();
        if (kt + 2 < 16) ISSUE(kt + 2);

        const float* as = smem + (kt % NSTAGE) * AS_ELE;
        const float* bs = smem + NSTAGE * AS_ELE + (kt % NSTAGE) * BS_ELE;
#pragma unroll
        for (int ks = 0; ks < 4; ks++) {
            uint32_t af[4][4], bf[4][2];
            const int kk = ks * 8 + (lane & 3);
#pragma unroll
            for (int i = 0; i < 4; i++) {
                const int r = wm * 64 + i * 16 + (lane >> 2);
                af[i][0] = __float_as_uint(as[r * AS_STR + kk]);
                af[i][1] = __float_as_uint(as[(r + 8) * AS_STR + kk]);
                af[i][2] = __float_as_uint(as[r * AS_STR + kk + 4]);
                af[i][3] = __float_as_uint(as[(r + 8) * AS_STR + kk + 4]);
            }
#pragma unroll
            for (int j = 0; j < 4; j++) {
                const int c = wn * 32 + j * 8 + (lane >> 2);
                bf[j][0] = __float_as_uint(bs[kk * BS_STR + c]);
                bf[j][1] = __float_as_uint(bs[(kk + 4) * BS_STR + c]);
            }
#pragma unroll
            for (int i = 0; i < 4; i++)
#pragma unroll
                for (int j = 0; j < 4; j++)
                    mma_tf32(acc[i][j], af[i], bf[j]);
        }
    }

    // epilogue
#pragma unroll
    for (int i = 0; i < 4; i++) {
        const int rbase = m0 + wm * 64 + i * 16 + (lane >> 2);
#pragma unroll
        for (int h = 0; h < 2; h++) {
            const int gm = rbase + h * 8;
            if (gm < N_NODES) {
                const float invdeg = 1.0f / g_deg[gm];
#pragma unroll
                for (int j = 0; j < 4; j++) {
                    const int cb = n0 + wn * 32 + j * 8 + ((lane & 3) << 1);
                    const size_t o = (size_t)gm * 512 + cb;
                    const float v0 = acc[i][j][h * 2 + 0];
                    const float v1 = acc[i][j][h * 2 + 1];
                    *(float2*)(g_xw + o) = make_float2(v0, v1);
                    const float2 a2 = *(const float2*)(A + o);
                    const float2 b2 = *(const float2*)(bias + cb);
                    *(float2*)(g_acc + o) = make_float2(a2.x + b2.x + v0 * invdeg,
                                                        a2.y + b2.y + v1 * invdeg);
                }
            }
        }
    }
#undef ISSUE
}

// ---------------------------------------------------------------- CSR gather (atomic-free scatter replacement)
// One warp per destination node per feature slice; plain LDG+FFMA+ST.
// Sliced launches keep the src slice (~25MB) L2-resident.
__global__ void __launch_bounds__(256) k_gather(int slice) {
    const int n = blockIdx.x * WPB + (threadIdx.x >> 5);
    if (n >= N_NODES) return;
    const int cnt = min(g_slot[n], SLOTS);
    if (cnt == 0) return;
    const int t = threadIdx.x & 31;
    const int off = slice * SLICE_F + t * 4;
    float* dst = g_acc + (size_t)n * DIM + off;
    float4 a = *(const float4*)dst;
    const size_t base = (size_t)n * SLOTS;

    int i = 0;
    for (; i + 4 <= cnt; i += 4) {
        const int s0 = g_csr_src[base + i + 0];
        const int s1 = g_csr_src[base + i + 1];
        const int s2 = g_csr_src[base + i + 2];
        const int s3 = g_csr_src[base + i + 3];
        const float c0 = g_csr_cf[base + i + 0];
        const float c1 = g_csr_cf[base + i + 1];
        const float c2 = g_csr_cf[base + i + 2];
        const float c3 = g_csr_cf[base + i + 3];
        const float4 v0 = *(const float4*)(g_xw + (size_t)s0 * DIM + off);
        const float4 v1 = *(const float4*)(g_xw + (size_t)s1 * DIM + off);
        const float4 v2 = *(const float4*)(g_xw + (size_t)s2 * DIM + off);
        const float4 v3 = *(const float4*)(g_xw + (size_t)s3 * DIM + off);
        a.x += v0.x * c0 + v1.x * c1 + v2.x * c2 + v3.x * c3;
        a.y += v0.y * c0 + v1.y * c1 + v2.y * c2 + v3.y * c3;
        a.z += v0.z * c0 + v1.z * c1 + v2.z * c2 + v3.z * c3;
        a.w += v0.w * c0 + v1.w * c1 + v2.w * c2 + v3.w * c3;
    }
    if (i + 2 <= cnt) {
        const int s0 = g_csr_src[base + i + 0];
        const int s1 = g_csr_src[base + i + 1];
        const float c0 = g_csr_cf[base + i + 0];
        const float c1 = g_csr_cf[base + i + 1];
        const float4 v0 = *(const float4*)(g_xw + (size_t)s0 * DIM + off);
        const float4 v1 = *(const float4*)(g_xw + (size_t)s1 * DIM + off);
        a.x += v0.x * c0 + v1.x * c1;
        a.y += v0.y * c0 + v1.y * c1;
        a.z += v0.z * c0 + v1.z * c1;
        a.w += v0.w * c0 + v1.w * c1;
        i += 2;
    }
    if (i < cnt) {
        const int s0 = g_csr_src[base + i];
        const float c0 = g_csr_cf[base + i];
        const float4 v0 = *(const float4*)(g_xw + (size_t)s0 * DIM + off);
        a.x += v0.x * c0;
        a.y += v0.y * c0;
        a.z += v0.z * c0;
        a.w += v0.w * c0;
    }
    *(float4*)dst = a;
}

// ---------------------------------------------------------------- GraphNorm stats (single pass)
__global__ __launch_bounds__(256) void k_stats() {
    const int n0 = blockIdx.x * 128;
    const int nend = min(n0 + 128, N_NODES);
    const int t = threadIdx.x;
    const int d0 = t, d1 = t + 256;
    float s0 = 0.f, s1 = 0.f, q0 = 0.f, q1 = 0.f;
    int g = g_batch[n0], cnt = 0;
    for (int n = n0; n < nend; n++) {
        const int gn = g_batch[n];
        if (gn != g) {
            atomicAdd(&g_sum[g * DIM + d0], s0);
            atomicAdd(&g_sum[g * DIM + d1], s1);
            atomicAdd(&g_sq [g * DIM + d0], q0);
            atomicAdd(&g_sq [g * DIM + d1], q1);
            if (t == 0) atomicAdd(&g_cnt[g], (float)cnt);
            s0 = s1 = q0 = q1 = 0.f; cnt = 0; g = gn;
        }
        const float* row = g_acc + (size_t)n * DIM;
        const float x0 = row[d0], x1 = row[d1];
        s0 += x0; s1 += x1; q0 += x0 * x0; q1 += x1 * x1; cnt++;
    }
    atomicAdd(&g_sum[g * DIM + d0], s0);
    atomicAdd(&g_sum[g * DIM + d1], s1);
    atomicAdd(&g_sq [g * DIM + d0], q0);
    atomicAdd(&g_sq [g * DIM + d1], q1);
    if (t == 0) atomicAdd(&g_cnt[g], (float)cnt);
}

// ---------------------------------------------------------------- finalize: normalize + relu
__global__ __launch_bounds__(256) void k_final(const float* __restrict__ gw,
                                               const float* __restrict__ gb,
                                               const float* __restrict__ ms,
                                               float* __restrict__ out) {
    const int idx = blockIdx.x * blockDim.x + threadIdx.x;
    if (idx >= N_NODES * (DIM / 4)) return;
    const int n = idx >> 7;
    const int dc = (idx & 127) << 2;
    const int g = g_batch[n];
    const float ic = 1.f / fmaxf(g_cnt[g], 1.f);
    const float4 x  = *(const float4*)(g_acc + (size_t)n * DIM + dc);
    const float4 sm = *(const float4*)(g_sum + g * DIM + dc);
    const float4 sq = *(const float4*)(g_sq  + g * DIM + dc);
    const float4 w4 = *(const float4*)(gw + dc);
    const float4 b4 = *(const float4*)(gb + dc);
    const float4 m4 = *(const float4*)(ms + dc);
    float4 o;
    {
        const float m = sm.x * ic, c = m * m4.x;
        const float var = sq.x * ic - 2.f * c * m + c * c;
        o.x = fmaxf(w4.x * (x.x - c) * rsqrtf(var + EPSV) + b4.x, 0.f);
    }
    {
        const float m = sm.y * ic, c = m * m4.y;
        const float var = sq.y * ic - 2.f * c * m + c * c;
        o.y = fmaxf(w4.y * (x.y - c) * rsqrtf(var + EPSV) + b4.y, 0.f);
    }
    {
        const float m = sm.z * ic, c = m * m4.z;
        const float var = sq.z * ic - 2.f * c * m + c * c;
        o.z = fmaxf(w4.z * (x.z - c) * rsqrtf(var + EPSV) + b4.z, 0.f);
    }
    {
        const float m = sm.w * ic, c = m * m4.w;
        const float var = sq.w * ic - 2.f * c * m + c * c;
        o.w = fmaxf(w4.w * (x.w - c) * rsqrtf(var + EPSV) + b4.w, 0.f);
    }
    *(float4*)(out + (size_t)n * DIM + dc) = o;
}

// ---------------------------------------------------------------- launch
extern "C" void kernel_launch(void* const* d_in, const int* in_sizes, int n_in,
                              void* d_out, int out_size) {
    const float* node  = (const float*)d_in[0];
    const float* eattr = (const float*)d_in[1];
    const float* W     = (const float*)d_in[2];
    const float* b     = (const float*)d_in[3];
    const float* gw    = (const float*)d_in[4];
    const float* gb    = (const float*)d_in[5];
    const float* ms    = (const float*)d_in[6];
    const void*  ei    = d_in[7];
    const void*  batch = d_in[8];
    float* out = (float*)d_out;

    cudaFuncSetAttribute(k_gemm, cudaFuncAttributeMaxDynamicSharedMemorySize, SMEM_BYTES);

    k_init<<<(N_NODES + 255) / 256, 256>>>();
    k_convert<<<(N_EDGES + 255) / 256, 256>>>(ei, batch, eattr);
    k_fill<<<(N_EDGES + 255) / 256, 256>>>(eattr);
    {
        dim3 grid(DIM / 128, (N_NODES + 127) / 128);   // (4, 391)
        k_gemm<<<grid, 256, SMEM_BYTES>>>(node, W, b);
    }
    {
        const int blocks = (N_NODES + WPB - 1) / WPB;  // 6250
        for (int s = 0; s < NSLICE; s++)
            k_gather<<<blocks, 256>>>(s);
    }
    k_stats<<<(N_NODES + 127) / 128, 256>>>();
    k_final<<<(N_NODES * (DIM / 4) + 255) / 256, 256>>>(gw, gb, ms, out);
}

// round 12
// speedup vs baseline: 1.2467x; 1.1399x over previous
#include <cuda_runtime.h>
#include <cstdint>

#define N_NODES 50000
#define N_EDGES 160000
#define DIM     512
#define N_GRAPHS 64
#define EPSV    1e-5f

// GEMM tiling: BM=128, BN=128, BK=32, 3-stage cp.async, 8 warps, warp tile 64x32, 2 CTAs/SM
#define AS_STR 36
#define BS_STR 136
#define AS_ELE (128 * AS_STR)
#define BS_ELE (32 * BS_STR)
#define NSTAGE 3
#define SMEM_BYTES (NSTAGE * (AS_ELE + BS_ELE) * 4)   // 107520 B

// gather: padded CSR (32 slots/dst), 4 feature slices of 128 floats, 1 warp/dst
#define SLOTS 32
#define NSLICE 4
#define SLICE_F (DIM / NSLICE)
#define GW 8                            // warps (=nodes) per gather block

// ---- scratch (static __device__: allocation-free) ----
__device__ float g_xw [(size_t)N_NODES * DIM];
__device__ float g_acc[(size_t)N_NODES * DIM];
__device__ float g_deg[N_NODES];
__device__ int   g_slot[N_NODES];
__device__ int   g_csr_src[(size_t)N_NODES * SLOTS];
__device__ float g_csr_cf [(size_t)N_NODES * SLOTS];
__device__ float g_sum[N_GRAPHS * DIM];
__device__ float g_sq [N_GRAPHS * DIM];
__device__ float g_cnt[N_GRAPHS];
__device__ int   g_ei_row[N_EDGES];
__device__ int   g_ei_col[N_EDGES];
__device__ int   g_batch [N_NODES];

// ---------------------------------------------------------------- init
__global__ void k_init() {
    int i = blockIdx.x * blockDim.x + threadIdx.x;
    if (i < N_NODES) { g_deg[i] = 1.0f; g_slot[i] = 0; }
    if (i < N_GRAPHS * DIM) { g_sum[i] = 0.f; g_sq[i] = 0.f; }
    if (i < N_GRAPHS) g_cnt[i] = 0.f;
}

// ---------------------------------------------------------------- dtype-robust index conversion + degree
__global__ void k_convert(const void* __restrict__ ei, const void* __restrict__ batch,
                          const float* __restrict__ w) {
    __shared__ int s64;
    const int tid = threadIdx.x;
    if (tid == 0) {
        const long long* q = (const long long*)ei;
        int ok = 1;
#pragma unroll
        for (int i = 0; i < 8; i++) { long long v = q[i]; if (v < 0 || v >= N_NODES) ok = 0; }
        s64 = ok;
    }
    __syncthreads();
    const int is64 = s64;
    const int e = blockIdx.x * blockDim.x + tid;
    if (e < N_EDGES) {
        int r, c;
        if (is64) { r = (int)((const long long*)ei)[e]; c = (int)((const long long*)ei)[N_EDGES + e]; }
        else      { r = ((const int*)ei)[e];            c = ((const int*)ei)[N_EDGES + e]; }
        r = min(max(r, 0), N_NODES - 1);
        c = min(max(c, 0), N_NODES - 1);
        g_ei_row[e] = r;
        g_ei_col[e] = c;
        atomicAdd(&g_deg[c], w[e]);
    }
    if (e < N_NODES) {
        int bv = is64 ? (int)((const long long*)batch)[e] : ((const int*)batch)[e];
        g_batch[e] = min(max(bv, 0), N_GRAPHS - 1);
    }
}

// ---------------------------------------------------------------- CSR fill (after deg final)
__global__ void k_fill(const float* __restrict__ w) {
    const int e = blockIdx.x * blockDim.x + threadIdx.x;
    if (e >= N_EDGES) return;
    const int r = g_ei_row[e];
    const int c = g_ei_col[e];
    const float coef = w[e] * rsqrtf(g_deg[r]) * rsqrtf(g_deg[c]);
    const int slot = atomicAdd(&g_slot[c], 1);
    if (slot < SLOTS) {
        g_csr_src[(size_t)c * SLOTS + slot] = r;
        g_csr_cf [(size_t)c * SLOTS + slot] = coef;
    }
}

// ---------------------------------------------------------------- helpers
__device__ __forceinline__ void cpasync16(uint32_t dst, const void* src) {
    asm volatile("cp.async.cg.shared.global [%0], [%1], 16;" :: "r"(dst), "l"(src));
}
#define CP_COMMIT()  asm volatile("cp.async.commit_group;" ::: "memory")
#define CP_WAIT(n)   asm volatile("cp.async.wait_group %0;" :: "n"(n) : "memory")
__device__ __forceinline__ uint32_t smem_u32(const void* p) {
    uint32_t a;
    asm("{ .reg .u64 t; cvta.to.shared.u64 t, %1; cvt.u32.u64 %0, t; }" : "=r"(a) : "l"(p));
    return a;
}
__device__ __forceinline__ void mma_tf32(float* d, const uint32_t* a, const uint32_t* b) {
    asm volatile(
        "mma.sync.aligned.m16n8k8.row.col.f32.tf32.tf32.f32 "
        "{%0,%1,%2,%3},{%4,%5,%6,%7},{%8,%9},{%0,%1,%2,%3};\n"
        : "+f"(d[0]), "+f"(d[1]), "+f"(d[2]), "+f"(d[3])
        : "r"(a[0]), "r"(a[1]), "r"(a[2]), "r"(a[3]), "r"(b[0]), "r"(b[1]));
}
__device__ __forceinline__ void red4(float* p, float4 v) {
    asm volatile("red.global.add.v4.f32 [%0], {%1,%2,%3,%4};"
                 :: "l"(p), "f"(v.x), "f"(v.y), "f"(v.z), "f"(v.w) : "memory");
}

// ---------------------------------------------------------------- GEMM (epilogue writes g_xw only)
__global__ void __launch_bounds__(256, 2) k_gemm(
    const float* __restrict__ A,
    const float* __restrict__ B)
{
    extern __shared__ float smem[];
    const uint32_t sbase = smem_u32(smem);
    const int tid  = threadIdx.x;
    const int lane = tid & 31;
    const int warp = tid >> 5;
    const int wm = warp >> 2;   // 0..1
    const int wn = warp & 3;    // 0..3
    const int m0 = blockIdx.y * 128;
    const int n0 = blockIdx.x * 128;

    float acc[4][4][4];
#pragma unroll
    for (int i = 0; i < 4; i++)
#pragma unroll
        for (int j = 0; j < 4; j++)
#pragma unroll
            for (int c = 0; c < 4; c++) acc[i][j][c] = 0.f;

#define ISSUE(KT) do {                                                           \
        const int kk = (KT) * 32;                                                \
        const uint32_t sa = sbase + ((KT) % NSTAGE) * (AS_ELE * 4);              \
        const uint32_t sbb = sbase + (NSTAGE * AS_ELE + ((KT) % NSTAGE) * BS_ELE) * 4; \
        _Pragma("unroll")                                                        \
        for (int i = 0; i < 4; i++) {                                            \
            const int idx = tid + i * 256;                                       \
            const int row = idx >> 3, col = (idx & 7) * 4;                       \
            int gm = m0 + row;                                                   \
            if (gm >= N_NODES) gm = N_NODES - 1;                                 \
            cpasync16(sa + (uint32_t)(row * AS_STR + col) * 4,                   \
                      A + (size_t)gm * 512 + kk + col);                          \
        }                                                                        \
        _Pragma("unroll")                                                        \
        for (int i = 0; i < 4; i++) {                                            \
            const int idx = tid + i * 256;                                       \
            const int row = idx >> 5, col = (idx & 31) * 4;                      \
            cpasync16(sbb + (uint32_t)(row * BS_STR + col) * 4,                  \
                      B + (size_t)(kk + row) * 512 + n0 + col);                  \
        }                                                                        \
        CP_COMMIT();                                                             \
    } while (0)

    ISSUE(0);
    ISSUE(1);

#pragma unroll 1
    for (int kt = 0; kt < 16; kt++) {
        CP_WAIT(1);
        __syncthreads();
        if (kt + 2 < 16) ISSUE(kt + 2);

        const float* as = smem + (kt % NSTAGE) * AS_ELE;
        const float* bs = smem + NSTAGE * AS_ELE + (kt % NSTAGE) * BS_ELE;
#pragma unroll
        for (int ks = 0; ks < 4; ks++) {
            uint32_t af[4][4], bf[4][2];
            const int kk = ks * 8 + (lane & 3);
#pragma unroll
            for (int i = 0; i < 4; i++) {
                const int r = wm * 64 + i * 16 + (lane >> 2);
                af[i][0] = __float_as_uint(as[r * AS_STR + kk]);
                af[i][1] = __float_as_uint(as[(r + 8) * AS_STR + kk]);
                af[i][2] = __float_as_uint(as[r * AS_STR + kk + 4]);
                af[i][3] = __float_as_uint(as[(r + 8) * AS_STR + kk + 4]);
            }
#pragma unroll
            for (int j = 0; j < 4; j++) {
                const int c = wn * 32 + j * 8 + (lane >> 2);
                bf[j][0] = __float_as_uint(bs[kk * BS_STR + c]);
                bf[j][1] = __float_as_uint(bs[(kk + 4) * BS_STR + c]);
            }
#pragma unroll
            for (int i = 0; i < 4; i++)
#pragma unroll
                for (int j = 0; j < 4; j++)
                    mma_tf32(acc[i][j], af[i], bf[j]);
        }
    }

    // epilogue: write xw only
#pragma unroll
    for (int i = 0; i < 4; i++) {
        const int rbase = m0 + wm * 64 + i * 16 + (lane >> 2);
#pragma unroll
        for (int h = 0; h < 2; h++) {
            const int gm = rbase + h * 8;
            if (gm < N_NODES) {
#pragma unroll
                for (int j = 0; j < 4; j++) {
                    const int cb = n0 + wn * 32 + j * 8 + ((lane & 3) << 1);
                    *(float2*)(g_xw + (size_t)gm * 512 + cb) =
                        make_float2(acc[i][j][h * 2 + 0], acc[i][j][h * 2 + 1]);
                }
            }
        }
    }
#undef ISSUE
}

// ---------------------------------------------------------------- CSR gather + skip/bias/self fused + GraphNorm stats
// One warp per node per 128-dim slice. Computes final g_acc value, then
// block-reduces sum/sumsq across the 8 (sorted, usually same-graph) nodes
// and fires vec4 REDs into g_sum/g_sq.
__global__ void __launch_bounds__(256) k_gather(const float* __restrict__ node,
                                                const float* __restrict__ bias,
                                                int slice) {
    __shared__ float s_sum[GW][SLICE_F];
    __shared__ float s_sq [GW][SLICE_F];
    __shared__ int   s_gid[GW];
    const int w = threadIdx.x >> 5;
    const int t = threadIdx.x & 31;
    const int n = blockIdx.x * GW + w;          // 6250*8 = 50000 exactly
    const int off = slice * SLICE_F + t * 4;

    float4 a = make_float4(0.f, 0.f, 0.f, 0.f);
    int g = -1;
    if (n < N_NODES) {
        g = g_batch[n];
        const int cnt = min(g_slot[n], SLOTS);
        const float invdeg = 1.0f / g_deg[n];
        const float4 xn = *(const float4*)(g_xw + (size_t)n * DIM + off);
        const float4 nd = *(const float4*)(node + (size_t)n * DIM + off);
        const float4 b4 = *(const float4*)(bias + off);
        a.x = nd.x + b4.x + xn.x * invdeg;
        a.y = nd.y + b4.y + xn.y * invdeg;
        a.z = nd.z + b4.z + xn.z * invdeg;
        a.w = nd.w + b4.w + xn.w * invdeg;

        const size_t base = (size_t)n * SLOTS;
        int i = 0;
        for (; i + 4 <= cnt; i += 4) {
            const int s0 = g_csr_src[base + i + 0];
            const int s1 = g_csr_src[base + i + 1];
            const int s2 = g_csr_src[base + i + 2];
            const int s3 = g_csr_src[base + i + 3];
            const float c0 = g_csr_cf[base + i + 0];
            const float c1 = g_csr_cf[base + i + 1];
            const float c2 = g_csr_cf[base + i + 2];
            const float c3 = g_csr_cf[base + i + 3];
            const float4 v0 = *(const float4*)(g_xw + (size_t)s0 * DIM + off);
            const float4 v1 = *(const float4*)(g_xw + (size_t)s1 * DIM + off);
            const float4 v2 = *(const float4*)(g_xw + (size_t)s2 * DIM + off);
            const float4 v3 = *(const float4*)(g_xw + (size_t)s3 * DIM + off);
            a.x += v0.x * c0 + v1.x * c1 + v2.x * c2 + v3.x * c3;
            a.y += v0.y * c0 + v1.y * c1 + v2.y * c2 + v3.y * c3;
            a.z += v0.z * c0 + v1.z * c1 + v2.z * c2 + v3.z * c3;
            a.w += v0.w * c0 + v1.w * c1 + v2.w * c2 + v3.w * c3;
        }
        for (; i < cnt; i++) {
            const int s0 = g_csr_src[base + i];
            const float c0 = g_csr_cf[base + i];
            const float4 v0 = *(const float4*)(g_xw + (size_t)s0 * DIM + off);
            a.x += v0.x * c0; a.y += v0.y * c0; a.z += v0.z * c0; a.w += v0.w * c0;
        }
        *(float4*)(g_acc + (size_t)n * DIM + off) = a;
        if (slice == 0 && t == 0) atomicAdd(&g_cnt[g], 1.0f);
    }
    if (t == 0) s_gid[w] = g;
    *(float4*)&s_sum[w][t * 4] = a;
    *(float4*)&s_sq [w][t * 4] = make_float4(a.x * a.x, a.y * a.y, a.z * a.z, a.w * a.w);
    __syncthreads();

    if (w == 0) {
        const int g0 = s_gid[0];
        bool uni = true;
#pragma unroll
        for (int i = 1; i < GW; i++) {
            const int gi = s_gid[i];
            uni &= (gi == g0 || gi < 0);
        }
        const int d4 = t * 4;           // 32 lanes x 4 = 128 dims
        if (uni) {
            if (g0 >= 0) {
                float4 S = make_float4(0.f, 0.f, 0.f, 0.f);
                float4 Q = make_float4(0.f, 0.f, 0.f, 0.f);
#pragma unroll
                for (int i = 0; i < GW; i++) {
                    const float4 p = *(const float4*)&s_sum[i][d4];
                    const float4 q = *(const float4*)&s_sq[i][d4];
                    S.x += p.x; S.y += p.y; S.z += p.z; S.w += p.w;
                    Q.x += q.x; Q.y += q.y; Q.z += q.z; Q.w += q.w;
                }
                red4(&g_sum[g0 * DIM + off], S);
                red4(&g_sq [g0 * DIM + off], Q);
            }
        } else {
#pragma unroll 1
            for (int i = 0; i < GW; i++) {
                const int gi = s_gid[i];
                if (gi >= 0) {
                    red4(&g_sum[gi * DIM + off], *(const float4*)&s_sum[i][d4]);
                    red4(&g_sq [gi * DIM + off], *(const float4*)&s_sq[i][d4]);
                }
            }
        }
    }
}

// ---------------------------------------------------------------- finalize: normalize + relu
__global__ __launch_bounds__(256) void k_final(const float* __restrict__ gw,
                                               const float* __restrict__ gb,
                                               const float* __restrict__ ms,
                                               float* __restrict__ out) {
    const int idx = blockIdx.x * blockDim.x + threadIdx.x;
    if (idx >= N_NODES * (DIM / 4)) return;
    const int n = idx >> 7;
    const int dc = (idx & 127) << 2;
    const int g = g_batch[n];
    const float ic = 1.f / fmaxf(g_cnt[g], 1.f);
    const float4 x  = *(const float4*)(g_acc + (size_t)n * DIM + dc);
    const float4 sm = *(const float4*)(g_sum + g * DIM + dc);
    const float4 sq = *(const float4*)(g_sq  + g * DIM + dc);
    const float4 w4 = *(const float4*)(gw + dc);
    const float4 b4 = *(const float4*)(gb + dc);
    const float4 m4 = *(const float4*)(ms + dc);
    float4 o;
    {
        const float m = sm.x * ic, c = m * m4.x;
        const float var = sq.x * ic - 2.f * c * m + c * c;
        o.x = fmaxf(w4.x * (x.x - c) * rsqrtf(var + EPSV) + b4.x, 0.f);
    }
    {
        const float m = sm.y * ic, c = m * m4.y;
        const float var = sq.y * ic - 2.f * c * m + c * c;
        o.y = fmaxf(w4.y * (x.y - c) * rsqrtf(var + EPSV) + b4.y, 0.f);
    }
    {
        const float m = sm.z * ic, c = m * m4.z;
        const float var = sq.z * ic - 2.f * c * m + c * c;
        o.z = fmaxf(w4.z * (x.z - c) * rsqrtf(var + EPSV) + b4.z, 0.f);
    }
    {
        const float m = sm.w * ic, c = m * m4.w;
        const float var = sq.w * ic - 2.f * c * m + c * c;
        o.w = fmaxf(w4.w * (x.w - c) * rsqrtf(var + EPSV) + b4.w, 0.f);
    }
    *(float4*)(out + (size_t)n * DIM + dc) = o;
}

// ---------------------------------------------------------------- launch
extern "C" void kernel_launch(void* const* d_in, const int* in_sizes, int n_in,
                              void* d_out, int out_size) {
    const float* node  = (const float*)d_in[0];
    const float* eattr = (const float*)d_in[1];
    const float* W     = (const float*)d_in[2];
    const float* b     = (const float*)d_in[3];
    const float* gw    = (const float*)d_in[4];
    const float* gb    = (const float*)d_in[5];
    const float* ms    = (const float*)d_in[6];
    const void*  ei    = d_in[7];
    const void*  batch = d_in[8];
    float* out = (float*)d_out;

    cudaFuncSetAttribute(k_gemm, cudaFuncAttributeMaxDynamicSharedMemorySize, SMEM_BYTES);

    k_init<<<(N_NODES + 255) / 256, 256>>>();
    k_convert<<<(N_EDGES + 255) / 256, 256>>>(ei, batch, eattr);
    k_fill<<<(N_EDGES + 255) / 256, 256>>>(eattr);
    {
        dim3 grid(DIM / 128, (N_NODES + 127) / 128);   // (4, 391)
        k_gemm<<<grid, 256, SMEM_BYTES>>>(node, W);
    }
    {
        const int blocks = (N_NODES + GW - 1) / GW;    // 6250
        for (int s = 0; s < NSLICE; s++)
            k_gather<<<blocks, 256>>>(node, b, s);
    }
    k_final<<<(N_NODES * (DIM / 4) + 255) / 256, 256>>>(gw, gb, ms, out);
}

// round 13
// speedup vs baseline: 1.3164x; 1.0559x over previous
#include <cuda_runtime.h>
#include <cstdint>

#define N_NODES 50000
#define N_EDGES 160000
#define DIM     512
#define N_GRAPHS 64
#define EPSV    1e-5f

// GEMM tiling: BM=128, BN=128, BK=32, 3-stage cp.async, 8 warps, warp tile 64x32, 2 CTAs/SM
#define AS_STR 36
#define BS_STR 136
#define AS_ELE (128 * AS_STR)
#define BS_ELE (32 * BS_STR)
#define NSTAGE 3
#define SMEM_BYTES (NSTAGE * (AS_ELE + BS_ELE) * 4)   // 107520 B

// gather: padded CSR (32 slots/dst), 2 feature slices of 256 floats, 1 warp/dst
#define SLOTS 32
#define NSLICE 2
#define SLICE_F (DIM / NSLICE)          // 256
#define GW 8                            // warps (=nodes) per gather block

// ---- scratch (static __device__: allocation-free) ----
__device__ float g_xw [(size_t)N_NODES * DIM];
__device__ float g_acc[(size_t)N_NODES * DIM];
__device__ float g_deg[N_NODES];
__device__ int   g_slot[N_NODES];
__device__ int   g_csr_src[(size_t)N_NODES * SLOTS];
__device__ float g_csr_cf [(size_t)N_NODES * SLOTS];
__device__ float g_sum[N_GRAPHS * DIM];
__device__ float g_sq [N_GRAPHS * DIM];
__device__ float g_cnt[N_GRAPHS];
__device__ int   g_ei_row[N_EDGES];
__device__ int   g_ei_col[N_EDGES];
__device__ int   g_batch [N_NODES];

// ---------------------------------------------------------------- init
__global__ void k_init() {
    int i = blockIdx.x * blockDim.x + threadIdx.x;
    if (i < N_NODES) { g_deg[i] = 1.0f; g_slot[i] = 0; }
    if (i < N_GRAPHS * DIM) { g_sum[i] = 0.f; g_sq[i] = 0.f; }
    if (i < N_GRAPHS) g_cnt[i] = 0.f;
}

// ---------------------------------------------------------------- dtype-robust index conversion + degree
__global__ void k_convert(const void* __restrict__ ei, const void* __restrict__ batch,
                          const float* __restrict__ w) {
    __shared__ int s64;
    const int tid = threadIdx.x;
    if (tid == 0) {
        const long long* q = (const long long*)ei;
        int ok = 1;
#pragma unroll
        for (int i = 0; i < 8; i++) { long long v = q[i]; if (v < 0 || v >= N_NODES) ok = 0; }
        s64 = ok;
    }
    __syncthreads();
    const int is64 = s64;
    const int e = blockIdx.x * blockDim.x + tid;
    if (e < N_EDGES) {
        int r, c;
        if (is64) { r = (int)((const long long*)ei)[e]; c = (int)((const long long*)ei)[N_EDGES + e]; }
        else      { r = ((const int*)ei)[e];            c = ((const int*)ei)[N_EDGES + e]; }
        r = min(max(r, 0), N_NODES - 1);
        c = min(max(c, 0), N_NODES - 1);
        g_ei_row[e] = r;
        g_ei_col[e] = c;
        atomicAdd(&g_deg[c], w[e]);
    }
    if (e < N_NODES) {
        int bv = is64 ? (int)((const long long*)batch)[e] : ((const int*)batch)[e];
        g_batch[e] = min(max(bv, 0), N_GRAPHS - 1);
    }
}

// ---------------------------------------------------------------- CSR fill (after deg final)
__global__ void k_fill(const float* __restrict__ w) {
    const int e = blockIdx.x * blockDim.x + threadIdx.x;
    if (e >= N_EDGES) return;
    const int r = g_ei_row[e];
    const int c = g_ei_col[e];
    const float coef = w[e] * rsqrtf(g_deg[r]) * rsqrtf(g_deg[c]);
    const int slot = atomicAdd(&g_slot[c], 1);
    if (slot < SLOTS) {
        g_csr_src[(size_t)c * SLOTS + slot] = r;
        g_csr_cf [(size_t)c * SLOTS + slot] = coef;
    }
}

// ---------------------------------------------------------------- helpers
__device__ __forceinline__ void cpasync16(uint32_t dst, const void* src) {
    asm volatile("cp.async.cg.shared.global [%0], [%1], 16;" :: "r"(dst), "l"(src));
}
#define CP_COMMIT()  asm volatile("cp.async.commit_group;" ::: "memory")
#define CP_WAIT(n)   asm volatile("cp.async.wait_group %0;" :: "n"(n) : "memory")
__device__ __forceinline__ uint32_t smem_u32(const void* p) {
    uint32_t a;
    asm("{ .reg .u64 t; cvta.to.shared.u64 t, %1; cvt.u32.u64 %0, t; }" : "=r"(a) : "l"(p));
    return a;
}
__device__ __forceinline__ void mma_tf32(float* d, const uint32_t* a, const uint32_t* b) {
    asm volatile(
        "mma.sync.aligned.m16n8k8.row.col.f32.tf32.tf32.f32 "
        "{%0,%1,%2,%3},{%4,%5,%6,%7},{%8,%9},{%0,%1,%2,%3};\n"
        : "+f"(d[0]), "+f"(d[1]), "+f"(d[2]), "+f"(d[3])
        : "r"(a[0]), "r"(a[1]), "r"(a[2]), "r"(a[3]), "r"(b[0]), "r"(b[1]));
}
__device__ __forceinline__ void red4(float* p, float4 v) {
    asm volatile("red.global.add.v4.f32 [%0], {%1,%2,%3,%4};"
                 :: "l"(p), "f"(v.x), "f"(v.y), "f"(v.z), "f"(v.w) : "memory");
}
__device__ __forceinline__ void acc4(float4& a, float4 v, float c) {
    a.x += v.x * c; a.y += v.y * c; a.z += v.z * c; a.w += v.w * c;
}

// ---------------------------------------------------------------- GEMM (epilogue writes g_xw only)
__global__ void __launch_bounds__(256, 2) k_gemm(
    const float* __restrict__ A,
    const float* __restrict__ B)
{
    extern __shared__ float smem[];
    const uint32_t sbase = smem_u32(smem);
    const int tid  = threadIdx.x;
    const int lane = tid & 31;
    const int warp = tid >> 5;
    const int wm = warp >> 2;   // 0..1
    const int wn = warp & 3;    // 0..3
    const int m0 = blockIdx.y * 128;
    const int n0 = blockIdx.x * 128;

    float acc[4][4][4];
#pragma unroll
    for (int i = 0; i < 4; i++)
#pragma unroll
        for (int j = 0; j < 4; j++)
#pragma unroll
            for (int c = 0; c < 4; c++) acc[i][j][c] = 0.f;

#define ISSUE(KT) do {                                                           \
        const int kk = (KT) * 32;                                                \
        const uint32_t sa = sbase + ((KT) % NSTAGE) * (AS_ELE * 4);              \
        const uint32_t sbb = sbase + (NSTAGE * AS_ELE + ((KT) % NSTAGE) * BS_ELE) * 4; \
        _Pragma("unroll")                                                        \
        for (int i = 0; i < 4; i++) {                                            \
            const int idx = tid + i * 256;                                       \
            const int row = idx >> 3, col = (idx & 7) * 4;                       \
            int gm = m0 + row;                                                   \
            if (gm >= N_NODES) gm = N_NODES - 1;                                 \
            cpasync16(sa + (uint32_t)(row * AS_STR + col) * 4,                   \
                      A + (size_t)gm * 512 + kk + col);                          \
        }                                                                        \
        _Pragma("unroll")                                                        \
        for (int i = 0; i < 4; i++) {                                            \
            const int idx = tid + i * 256;                                       \
            const int row = idx >> 5, col = (idx & 31) * 4;                      \
            cpasync16(sbb + (uint32_t)(row * BS_STR + col) * 4,                  \
                      B + (size_t)(kk + row) * 512 + n0 + col);                  \
        }                                                                        \
        CP_COMMIT();                                                             \
    } while (0)

    ISSUE(0);
    ISSUE(1);

#pragma unroll 1
    for (int kt = 0; kt < 16; kt++) {
        CP_WAIT(1);
        __syncthreads();
        if (kt + 2 < 16) ISSUE(kt + 2);

        const float* as = smem + (kt % NSTAGE) * AS_ELE;
        const float* bs = smem + NSTAGE * AS_ELE + (kt % NSTAGE) * BS_ELE;
#pragma unroll
        for (int ks = 0; ks < 4; ks++) {
            uint32_t af[4][4], bf[4][2];
            const int kk = ks * 8 + (lane & 3);
#pragma unroll
            for (int i = 0; i < 4; i++) {
                const int r = wm * 64 + i * 16 + (lane >> 2);
                af[i][0] = __float_as_uint(as[r * AS_STR + kk]);
                af[i][1] = __float_as_uint(as[(r + 8) * AS_STR + kk]);
                af[i][2] = __float_as_uint(as[r * AS_STR + kk + 4]);
                af[i][3] = __float_as_uint(as[(r + 8) * AS_STR + kk + 4]);
            }
#pragma unroll
            for (int j = 0; j < 4; j++) {
                const int c = wn * 32 + j * 8 + (lane >> 2);
                bf[j][0] = __float_as_uint(bs[kk * BS_STR + c]);
                bf[j][1] = __float_as_uint(bs[(kk + 4) * BS_STR + c]);
            }
#pragma unroll
            for (int i = 0; i < 4; i++)
#pragma unroll
                for (int j = 0; j < 4; j++)
                    mma_tf32(acc[i][j], af[i], bf[j]);
        }
    }

    // epilogue: write xw only
#pragma unroll
    for (int i = 0; i < 4; i++) {
        const int rbase = m0 + wm * 64 + i * 16 + (lane >> 2);
#pragma unroll
        for (int h = 0; h < 2; h++) {
            const int gm = rbase + h * 8;
            if (gm < N_NODES) {
#pragma unroll
                for (int j = 0; j < 4; j++) {
                    const int cb = n0 + wn * 32 + j * 8 + ((lane & 3) << 1);
                    *(float2*)(g_xw + (size_t)gm * 512 + cb) =
                        make_float2(acc[i][j][h * 2 + 0], acc[i][j][h * 2 + 1]);
                }
            }
        }
    }
#undef ISSUE
}

// ---------------------------------------------------------------- CSR gather + skip/bias/self fused + GraphNorm stats
// One warp per node per 256-dim slice (2 x float4 per lane). Computes final
// g_acc, then block-reduces sum/sumsq over the 8 sorted nodes into g_sum/g_sq.
__global__ void __launch_bounds__(256) k_gather(const float* __restrict__ node,
                                                const float* __restrict__ bias,
                                                int slice) {
    __shared__ float s_sum[GW][SLICE_F];
    __shared__ float s_sq [GW][SLICE_F];
    __shared__ int   s_gid[GW];
    const int w = threadIdx.x >> 5;
    const int t = threadIdx.x & 31;
    const int n = blockIdx.x * GW + w;          // 6250*8 = 50000 exactly
    const int off = slice * SLICE_F + t * 4;    // second half at off+128

    float4 a0 = make_float4(0.f, 0.f, 0.f, 0.f);
    float4 a1 = make_float4(0.f, 0.f, 0.f, 0.f);
    int g = -1;
    if (n < N_NODES) {
        g = g_batch[n];
        const int cnt = min(g_slot[n], SLOTS);
        const float invdeg = 1.0f / g_deg[n];
        const size_t nb = (size_t)n * DIM + off;
        {
            const float4 xa = *(const float4*)(g_xw + nb);
            const float4 xb = *(const float4*)(g_xw + nb + 128);
            const float4 na = *(const float4*)(node + nb);
            const float4 nbv = *(const float4*)(node + nb + 128);
            const float4 ba = *(const float4*)(bias + off);
            const float4 bb = *(const float4*)(bias + off + 128);
            a0.x = na.x + ba.x + xa.x * invdeg;  a0.y = na.y + ba.y + xa.y * invdeg;
            a0.z = na.z + ba.z + xa.z * invdeg;  a0.w = na.w + ba.w + xa.w * invdeg;
            a1.x = nbv.x + bb.x + xb.x * invdeg; a1.y = nbv.y + bb.y + xb.y * invdeg;
            a1.z = nbv.z + bb.z + xb.z * invdeg; a1.w = nbv.w + bb.w + xb.w * invdeg;
        }

        const size_t base = (size_t)n * SLOTS;
        int i = 0;
        for (; i + 4 <= cnt; i += 4) {
            const int s0 = g_csr_src[base + i + 0];
            const int s1 = g_csr_src[base + i + 1];
            const int s2 = g_csr_src[base + i + 2];
            const int s3 = g_csr_src[base + i + 3];
            const float c0 = g_csr_cf[base + i + 0];
            const float c1 = g_csr_cf[base + i + 1];
            const float c2 = g_csr_cf[base + i + 2];
            const float c3 = g_csr_cf[base + i + 3];
            const size_t o0 = (size_t)s0 * DIM + off;
            const size_t o1 = (size_t)s1 * DIM + off;
            const size_t o2 = (size_t)s2 * DIM + off;
            const size_t o3 = (size_t)s3 * DIM + off;
            acc4(a0, *(const float4*)(g_xw + o0), c0);
            acc4(a1, *(const float4*)(g_xw + o0 + 128), c0);
            acc4(a0, *(const float4*)(g_xw + o1), c1);
            acc4(a1, *(const float4*)(g_xw + o1 + 128), c1);
            acc4(a0, *(const float4*)(g_xw + o2), c2);
            acc4(a1, *(const float4*)(g_xw + o2 + 128), c2);
            acc4(a0, *(const float4*)(g_xw + o3), c3);
            acc4(a1, *(const float4*)(g_xw + o3 + 128), c3);
        }
        if (i + 2 <= cnt) {
            const int s0 = g_csr_src[base + i + 0];
            const int s1 = g_csr_src[base + i + 1];
            const float c0 = g_csr_cf[base + i + 0];
            const float c1 = g_csr_cf[base + i + 1];
            const size_t o0 = (size_t)s0 * DIM + off;
            const size_t o1 = (size_t)s1 * DIM + off;
            acc4(a0, *(const float4*)(g_xw + o0), c0);
            acc4(a1, *(const float4*)(g_xw + o0 + 128), c0);
            acc4(a0, *(const float4*)(g_xw + o1), c1);
            acc4(a1, *(const float4*)(g_xw + o1 + 128), c1);
            i += 2;
        }
        if (i < cnt) {
            const int s0 = g_csr_src[base + i];
            const float c0 = g_csr_cf[base + i];
            const size_t o0 = (size_t)s0 * DIM + off;
            acc4(a0, *(const float4*)(g_xw + o0), c0);
            acc4(a1, *(const float4*)(g_xw + o0 + 128), c0);
        }
        *(float4*)(g_acc + nb) = a0;
        *(float4*)(g_acc + nb + 128) = a1;
        if (slice == 0 && t == 0) atomicAdd(&g_cnt[g], 1.0f);
    }
    if (t == 0) s_gid[w] = g;
    *(float4*)&s_sum[w][t * 4] = a0;
    *(float4*)&s_sum[w][128 + t * 4] = a1;
    *(float4*)&s_sq [w][t * 4] = make_float4(a0.x * a0.x, a0.y * a0.y, a0.z * a0.z, a0.w * a0.w);
    *(float4*)&s_sq [w][128 + t * 4] = make_float4(a1.x * a1.x, a1.y * a1.y, a1.z * a1.z, a1.w * a1.w);
    __syncthreads();

    if (w == 0) {
        const int g0 = s_gid[0];
        bool uni = true;
#pragma unroll
        for (int i = 1; i < GW; i++) {
            const int gi = s_gid[i];
            uni &= (gi == g0 || gi < 0);
        }
        if (uni) {
            if (g0 >= 0) {
#pragma unroll
                for (int hh = 0; hh < 2; hh++) {
                    const int d = hh * 128 + t * 4;
                    float4 S = make_float4(0.f, 0.f, 0.f, 0.f);
                    float4 Q = make_float4(0.f, 0.f, 0.f, 0.f);
#pragma unroll
                    for (int i = 0; i < GW; i++) {
                        const float4 p = *(const float4*)&s_sum[i][d];
                        const float4 q = *(const float4*)&s_sq[i][d];
                        S.x += p.x; S.y += p.y; S.z += p.z; S.w += p.w;
                        Q.x += q.x; Q.y += q.y; Q.z += q.z; Q.w += q.w;
                    }
                    red4(&g_sum[g0 * DIM + slice * SLICE_F + d], S);
                    red4(&g_sq [g0 * DIM + slice * SLICE_F + d], Q);
                }
            }
        } else {
#pragma unroll 1
            for (int i = 0; i < GW; i++) {
                const int gi = s_gid[i];
                if (gi >= 0) {
#pragma unroll
                    for (int hh = 0; hh < 2; hh++) {
                        const int d = hh * 128 + t * 4;
                        red4(&g_sum[gi * DIM + slice * SLICE_F + d],
                             *(const float4*)&s_sum[i][d]);
                        red4(&g_sq [gi * DIM + slice * SLICE_F + d],
                             *(const float4*)&s_sq[i][d]);
                    }
                }
            }
        }
    }
}

// ---------------------------------------------------------------- finalize: normalize + relu
__global__ __launch_bounds__(256) void k_final(const float* __restrict__ gw,
                                               const float* __restrict__ gb,
                                               const float* __restrict__ ms,
                                               float* __restrict__ out) {
    const int idx = blockIdx.x * blockDim.x + threadIdx.x;
    if (idx >= N_NODES * (DIM / 4)) return;
    const int n = idx >> 7;
    const int dc = (idx & 127) << 2;
    const int g = g_batch[n];
    const float ic = 1.f / fmaxf(g_cnt[g], 1.f);
    const float4 x  = *(const float4*)(g_acc + (size_t)n * DIM + dc);
    const float4 sm = *(const float4*)(g_sum + g * DIM + dc);
    const float4 sq = *(const float4*)(g_sq  + g * DIM + dc);
    const float4 w4 = *(const float4*)(gw + dc);
    const float4 b4 = *(const float4*)(gb + dc);
    const float4 m4 = *(const float4*)(ms + dc);
    float4 o;
    {
        const float m = sm.x * ic, c = m * m4.x;
        const float var = sq.x * ic - 2.f * c * m + c * c;
        o.x = fmaxf(w4.x * (x.x - c) * rsqrtf(var + EPSV) + b4.x, 0.f);
    }
    {
        const float m = sm.y * ic, c = m * m4.y;
        const float var = sq.y * ic - 2.f * c * m + c * c;
        o.y = fmaxf(w4.y * (x.y - c) * rsqrtf(var + EPSV) + b4.y, 0.f);
    }
    {
        const float m = sm.z * ic, c = m * m4.z;
        const float var = sq.z * ic - 2.f * c * m + c * c;
        o.z = fmaxf(w4.z * (x.z - c) * rsqrtf(var + EPSV) + b4.z, 0.f);
    }
    {
        const float m = sm.w * ic, c = m * m4.w;
        const float var = sq.w * ic - 2.f * c * m + c * c;
        o.w = fmaxf(w4.w * (x.w - c) * rsqrtf(var + EPSV) + b4.w, 0.f);
    }
    *(float4*)(out + (size_t)n * DIM + dc) = o;
}

// ---------------------------------------------------------------- launch
extern "C" void kernel_launch(void* const* d_in, const int* in_sizes, int n_in,
                              void* d_out, int out_size) {
    const float* node  = (const float*)d_in[0];
    const float* eattr = (const float*)d_in[1];
    const float* W     = (const float*)d_in[2];
    const float* b     = (const float*)d_in[3];
    const float* gw    = (const float*)d_in[4];
    const float* gb    = (const float*)d_in[5];
    const float* ms    = (const float*)d_in[6];
    const void*  ei    = d_in[7];
    const void*  batch = d_in[8];
    float* out = (float*)d_out;

    cudaFuncSetAttribute(k_gemm, cudaFuncAttributeMaxDynamicSharedMemorySize, SMEM_BYTES);

    k_init<<<(N_NODES + 255) / 256, 256>>>();
    k_convert<<<(N_EDGES + 255) / 256, 256>>>(ei, batch, eattr);
    k_fill<<<(N_EDGES + 255) / 256, 256>>>(eattr);
    {
        dim3 grid(DIM / 128, (N_NODES + 127) / 128);   // (4, 391)
        k_gemm<<<grid, 256, SMEM_BYTES>>>(node, W);
    }
    {
        const int blocks = (N_NODES + GW - 1) / GW;    // 6250
        for (int s = 0; s < NSLICE; s++)
            k_gather<<<blocks, 256>>>(node, b, s);
    }
    k_final<<<(N_NODES * (DIM / 4) + 255) / 256, 256>>>(gw, gb, ms, out);
}

// round 14
// speedup vs baseline: 1.4127x; 1.0732x over previous
#include <cuda_runtime.h>
#include <cstdint>

#define N_NODES 50000
#define N_EDGES 160000
#define DIM     512
#define N_GRAPHS 64
#define EPSV    1e-5f

// GEMM tiling: BM=128, BN=128, BK=32, 3-stage cp.async, 8 warps, warp tile 64x32, 2 CTAs/SM
#define AS_STR 36
#define BS_STR 136
#define AS_ELE (128 * AS_STR)
#define BS_ELE (32 * BS_STR)
#define NSTAGE 3
#define SMEM_BYTES (NSTAGE * (AS_ELE + BS_ELE) * 4)   // 107520 B

// gather: padded CSR (32 slots/dst), FULL row per warp (streaming hints keep xw in L2)
#define SLOTS 32
#define GW 8                            // warps (=nodes) per gather block

// ---- scratch (static __device__: allocation-free) ----
__device__ float g_xw [(size_t)N_NODES * DIM];
__device__ float g_acc[(size_t)N_NODES * DIM];
__device__ float g_deg[N_NODES];
__device__ int   g_slot[N_NODES];
__device__ int   g_csr_src[(size_t)N_NODES * SLOTS];
__device__ float g_csr_cf [(size_t)N_NODES * SLOTS];
__device__ float g_sum[N_GRAPHS * DIM];
__device__ float g_sq [N_GRAPHS * DIM];
__device__ float g_cnt[N_GRAPHS];
__device__ int   g_ei_row[N_EDGES];
__device__ int   g_ei_col[N_EDGES];
__device__ int   g_batch [N_NODES];

// ---------------------------------------------------------------- init
__global__ void k_init() {
    int i = blockIdx.x * blockDim.x + threadIdx.x;
    if (i < N_NODES) { g_deg[i] = 1.0f; g_slot[i] = 0; }
    if (i < N_GRAPHS * DIM) { g_sum[i] = 0.f; g_sq[i] = 0.f; }
    if (i < N_GRAPHS) g_cnt[i] = 0.f;
}

// ---------------------------------------------------------------- dtype-robust index conversion + degree
__global__ void k_convert(const void* __restrict__ ei, const void* __restrict__ batch,
                          const float* __restrict__ w) {
    __shared__ int s64;
    const int tid = threadIdx.x;
    if (tid == 0) {
        const long long* q = (const long long*)ei;
        int ok = 1;
#pragma unroll
        for (int i = 0; i < 8; i++) { long long v = q[i]; if (v < 0 || v >= N_NODES) ok = 0; }
        s64 = ok;
    }
    __syncthreads();
    const int is64 = s64;
    const int e = blockIdx.x * blockDim.x + tid;
    if (e < N_EDGES) {
        int r, c;
        if (is64) { r = (int)((const long long*)ei)[e]; c = (int)((const long long*)ei)[N_EDGES + e]; }
        else      { r = ((const int*)ei)[e];            c = ((const int*)ei)[N_EDGES + e]; }
        r = min(max(r, 0), N_NODES - 1);
        c = min(max(c, 0), N_NODES - 1);
        g_ei_row[e] = r;
        g_ei_col[e] = c;
        atomicAdd(&g_deg[c], w[e]);
    }
    if (e < N_NODES) {
        int bv = is64 ? (int)((const long long*)batch)[e] : ((const int*)batch)[e];
        g_batch[e] = min(max(bv, 0), N_GRAPHS - 1);
    }
}

// ---------------------------------------------------------------- CSR fill (after deg final)
__global__ void k_fill(const float* __restrict__ w) {
    const int e = blockIdx.x * blockDim.x + threadIdx.x;
    if (e >= N_EDGES) return;
    const int r = g_ei_row[e];
    const int c = g_ei_col[e];
    const float coef = w[e] * rsqrtf(g_deg[r]) * rsqrtf(g_deg[c]);
    const int slot = atomicAdd(&g_slot[c], 1);
    if (slot < SLOTS) {
        g_csr_src[(size_t)c * SLOTS + slot] = r;
        g_csr_cf [(size_t)c * SLOTS + slot] = coef;
    }
}

// ---------------------------------------------------------------- helpers
__device__ __forceinline__ void cpasync16(uint32_t dst, const void* src) {
    asm volatile("cp.async.cg.shared.global [%0], [%1], 16;" :: "r"(dst), "l"(src));
}
#define CP_COMMIT()  asm volatile("cp.async.commit_group;" ::: "memory")
#define CP_WAIT(n)   asm volatile("cp.async.wait_group %0;" :: "n"(n) : "memory")
__device__ __forceinline__ uint32_t smem_u32(const void* p) {
    uint32_t a;
    asm("{ .reg .u64 t; cvta.to.shared.u64 t, %1; cvt.u32.u64 %0, t; }" : "=r"(a) : "l"(p));
    return a;
}
__device__ __forceinline__ void mma_tf32(float* d, const uint32_t* a, const uint32_t* b) {
    asm volatile(
        "mma.sync.aligned.m16n8k8.row.col.f32.tf32.tf32.f32 "
        "{%0,%1,%2,%3},{%4,%5,%6,%7},{%8,%9},{%0,%1,%2,%3};\n"
        : "+f"(d[0]), "+f"(d[1]), "+f"(d[2]), "+f"(d[3])
        : "r"(a[0]), "r"(a[1]), "r"(a[2]), "r"(a[3]), "r"(b[0]), "r"(b[1]));
}
__device__ __forceinline__ void red4(float* p, float4 v) {
    asm volatile("red.global.add.v4.f32 [%0], {%1,%2,%3,%4};"
                 :: "l"(p), "f"(v.x), "f"(v.y), "f"(v.z), "f"(v.w) : "memory");
}
__device__ __forceinline__ void acc4(float4& a, float4 v, float c) {
    a.x += v.x * c; a.y += v.y * c; a.z += v.z * c; a.w += v.w * c;
}

// ---------------------------------------------------------------- GEMM (epilogue writes g_xw only)
__global__ void __launch_bounds__(256, 2) k_gemm(
    const float* __restrict__ A,
    const float* __restrict__ B)
{
    extern __shared__ float smem[];
    const uint32_t sbase = smem_u32(smem);
    const int tid  = threadIdx.x;
    const int lane = tid & 31;
    const int warp = tid >> 5;
    const int wm = warp >> 2;   // 0..1
    const int wn = warp & 3;    // 0..3
    const int m0 = blockIdx.y * 128;
    const int n0 = blockIdx.x * 128;

    float acc[4][4][4];
#pragma unroll
    for (int i = 0; i < 4; i++)
#pragma unroll
        for (int j = 0; j < 4; j++)
#pragma unroll
            for (int c = 0; c < 4; c++) acc[i][j][c] = 0.f;

#define ISSUE(KT) do {                                                           \
        const int kk = (KT) * 32;                                                \
        const uint32_t sa = sbase + ((KT) % NSTAGE) * (AS_ELE * 4);              \
        const uint32_t sbb = sbase + (NSTAGE * AS_ELE + ((KT) % NSTAGE) * BS_ELE) * 4; \
        _Pragma("unroll")                                                        \
        for (int i = 0; i < 4; i++) {                                            \
            const int idx = tid + i * 256;                                       \
            const int row = idx >> 3, col = (idx & 7) * 4;                       \
            int gm = m0 + row;                                                   \
            if (gm >= N_NODES) gm = N_NODES - 1;                                 \
            cpasync16(sa + (uint32_t)(row * AS_STR + col) * 4,                   \
                      A + (size_t)gm * 512 + kk + col);                          \
        }                                                                        \
        _Pragma("unroll")                                                        \
        for (int i = 0; i < 4; i++) {                                            \
            const int idx = tid + i * 256;                                       \
            const int row = idx >> 5, col = (idx & 31) * 4;                      \
            cpasync16(sbb + (uint32_t)(row * BS_STR + col) * 4,                  \
                      B + (size_t)(kk + row) * 512 + n0 + col);                  \
        }                                                                        \
        CP_COMMIT();                                                             \
    } while (0)

    ISSUE(0);
    ISSUE(1);

#pragma unroll 1
    for (int kt = 0; kt < 16; kt++) {
        CP_WAIT(1);
        __syncthreads();
        if (kt + 2 < 16) ISSUE(kt + 2);

        const float* as = smem + (kt % NSTAGE) * AS_ELE;
        const float* bs = smem + NSTAGE * AS_ELE + (kt % NSTAGE) * BS_ELE;
#pragma unroll
        for (int ks = 0; ks < 4; ks++) {
            uint32_t af[4][4], bf[4][2];
            const int kk = ks * 8 + (lane & 3);
#pragma unroll
            for (int i = 0; i < 4; i++) {
                const int r = wm * 64 + i * 16 + (lane >> 2);
                af[i][0] = __float_as_uint(as[r * AS_STR + kk]);
                af[i][1] = __float_as_uint(as[(r + 8) * AS_STR + kk]);
                af[i][2] = __float_as_uint(as[r * AS_STR + kk + 4]);
                af[i][3] = __float_as_uint(as[(r + 8) * AS_STR + kk + 4]);
            }
#pragma unroll
            for (int j = 0; j < 4; j++) {
                const int c = wn * 32 + j * 8 + (lane >> 2);
                bf[j][0] = __float_as_uint(bs[kk * BS_STR + c]);
                bf[j][1] = __float_as_uint(bs[(kk + 4) * BS_STR + c]);
            }
#pragma unroll
            for (int i = 0; i < 4; i++)
#pragma unroll
                for (int j = 0; j < 4; j++)
                    mma_tf32(acc[i][j], af[i], bf[j]);
        }
    }

    // epilogue: write xw only
#pragma unroll
    for (int i = 0; i < 4; i++) {
        const int rbase = m0 + wm * 64 + i * 16 + (lane >> 2);
#pragma unroll
        for (int h = 0; h < 2; h++) {
            const int gm = rbase + h * 8;
            if (gm < N_NODES) {
#pragma unroll
                for (int j = 0; j < 4; j++) {
                    const int cb = n0 + wn * 32 + j * 8 + ((lane & 3) << 1);
                    *(float2*)(g_xw + (size_t)gm * 512 + cb) =
                        make_float2(acc[i][j][h * 2 + 0], acc[i][j][h * 2 + 1]);
                }
            }
        }
    }
#undef ISSUE
}

// ---------------------------------------------------------------- CSR gather: full row per warp
// One warp per node, all 512 dims (4 x float4 per lane).  Streaming data
// (node read / acc write) uses evict-first hints so the 100MB g_xw gather
// set stays L2-resident.  Fused: skip + bias + self-loop + GraphNorm stats.
__global__ void __launch_bounds__(256) k_gather(const float* __restrict__ node,
                                                const float* __restrict__ bias) {
    __shared__ float s_sum[GW][DIM];
    __shared__ float s_sq [GW][DIM];
    __shared__ int   s_gid[GW];
    const int w = threadIdx.x >> 5;
    const int t = threadIdx.x & 31;
    const int n = blockIdx.x * GW + w;          // 6250*8 = 50000 exactly
    const int off = t * 4;                      // quarters at +0,+128,+256,+384

    float4 a[4];
#pragma unroll
    for (int q = 0; q < 4; q++) a[q] = make_float4(0.f, 0.f, 0.f, 0.f);
    int g = -1;
    if (n < N_NODES) {
        g = g_batch[n];
        const int cnt = min(g_slot[n], SLOTS);
        const float invdeg = 1.0f / g_deg[n];
        const size_t nb = (size_t)n * DIM + off;
#pragma unroll
        for (int q = 0; q < 4; q++) {
            const float4 xn = *(const float4*)(g_xw + nb + q * 128);
            const float4 nd = __ldcs((const float4*)(node + nb + q * 128));
            const float4 b4 = *(const float4*)(bias + off + q * 128);
            a[q].x = nd.x + b4.x + xn.x * invdeg;
            a[q].y = nd.y + b4.y + xn.y * invdeg;
            a[q].z = nd.z + b4.z + xn.z * invdeg;
            a[q].w = nd.w + b4.w + xn.w * invdeg;
        }

        const size_t base = (size_t)n * SLOTS;
        int i = 0;
        for (; i + 2 <= cnt; i += 2) {
            const int s0 = g_csr_src[base + i + 0];
            const int s1 = g_csr_src[base + i + 1];
            const float c0 = g_csr_cf[base + i + 0];
            const float c1 = g_csr_cf[base + i + 1];
            const size_t o0 = (size_t)s0 * DIM + off;
            const size_t o1 = (size_t)s1 * DIM + off;
#pragma unroll
            for (int q = 0; q < 4; q++) {
                acc4(a[q], *(const float4*)(g_xw + o0 + q * 128), c0);
                acc4(a[q], *(const float4*)(g_xw + o1 + q * 128), c1);
            }
        }
        if (i < cnt) {
            const int s0 = g_csr_src[base + i];
            const float c0 = g_csr_cf[base + i];
            const size_t o0 = (size_t)s0 * DIM + off;
#pragma unroll
            for (int q = 0; q < 4; q++)
                acc4(a[q], *(const float4*)(g_xw + o0 + q * 128), c0);
        }
#pragma unroll
        for (int q = 0; q < 4; q++)
            __stcs((float4*)(g_acc + nb + q * 128), a[q]);
        if (t == 0) atomicAdd(&g_cnt[g], 1.0f);
    }
    if (t == 0) s_gid[w] = g;
#pragma unroll
    for (int q = 0; q < 4; q++) {
        *(float4*)&s_sum[w][off + q * 128] = a[q];
        *(float4*)&s_sq [w][off + q * 128] =
            make_float4(a[q].x * a[q].x, a[q].y * a[q].y, a[q].z * a[q].z, a[q].w * a[q].w);
    }
    __syncthreads();

    if (w == 0) {
        const int g0 = s_gid[0];
        bool uni = true;
#pragma unroll
        for (int i = 1; i < GW; i++) {
            const int gi = s_gid[i];
            uni &= (gi == g0 || gi < 0);
        }
        if (uni) {
            if (g0 >= 0) {
#pragma unroll
                for (int q = 0; q < 4; q++) {
                    const int d = q * 128 + off;
                    float4 S = make_float4(0.f, 0.f, 0.f, 0.f);
                    float4 Q = make_float4(0.f, 0.f, 0.f, 0.f);
#pragma unroll
                    for (int i = 0; i < GW; i++) {
                        const float4 p = *(const float4*)&s_sum[i][d];
                        const float4 r = *(const float4*)&s_sq[i][d];
                        S.x += p.x; S.y += p.y; S.z += p.z; S.w += p.w;
                        Q.x += r.x; Q.y += r.y; Q.z += r.z; Q.w += r.w;
                    }
                    red4(&g_sum[g0 * DIM + d], S);
                    red4(&g_sq [g0 * DIM + d], Q);
                }
            }
        } else {
#pragma unroll 1
            for (int i = 0; i < GW; i++) {
                const int gi = s_gid[i];
                if (gi >= 0) {
#pragma unroll
                    for (int q = 0; q < 4; q++) {
                        const int d = q * 128 + off;
                        red4(&g_sum[gi * DIM + d], *(const float4*)&s_sum[i][d]);
                        red4(&g_sq [gi * DIM + d], *(const float4*)&s_sq[i][d]);
                    }
                }
            }
        }
    }
}

// ---------------------------------------------------------------- finalize: normalize + relu
__global__ __launch_bounds__(256) void k_final(const float* __restrict__ gw,
                                               const float* __restrict__ gb,
                                               const float* __restrict__ ms,
                                               float* __restrict__ out) {
    const int idx = blockIdx.x * blockDim.x + threadIdx.x;
    if (idx >= N_NODES * (DIM / 4)) return;
    const int n = idx >> 7;
    const int dc = (idx & 127) << 2;
    const int g = g_batch[n];
    const float ic = 1.f / fmaxf(g_cnt[g], 1.f);
    const float4 x  = __ldcs((const float4*)(g_acc + (size_t)n * DIM + dc));
    const float4 sm = *(const float4*)(g_sum + g * DIM + dc);
    const float4 sq = *(const float4*)(g_sq  + g * DIM + dc);
    const float4 w4 = *(const float4*)(gw + dc);
    const float4 b4 = *(const float4*)(gb + dc);
    const float4 m4 = *(const float4*)(ms + dc);
    float4 o;
    {
        const float m = sm.x * ic, c = m * m4.x;
        const float var = sq.x * ic - 2.f * c * m + c * c;
        o.x = fmaxf(w4.x * (x.x - c) * rsqrtf(var + EPSV) + b4.x, 0.f);
    }
    {
        const float m = sm.y * ic, c = m * m4.y;
        const float var = sq.y * ic - 2.f * c * m + c * c;
        o.y = fmaxf(w4.y * (x.y - c) * rsqrtf(var + EPSV) + b4.y, 0.f);
    }
    {
        const float m = sm.z * ic, c = m * m4.z;
        const float var = sq.z * ic - 2.f * c * m + c * c;
        o.z = fmaxf(w4.z * (x.z - c) * rsqrtf(var + EPSV) + b4.z, 0.f);
    }
    {
        const float m = sm.w * ic, c = m * m4.w;
        const float var = sq.w * ic - 2.f * c * m + c * c;
        o.w = fmaxf(w4.w * (x.w - c) * rsqrtf(var + EPSV) + b4.w, 0.f);
    }
    __stcs((float4*)(out + (size_t)n * DIM + dc), o);
}

// ---------------------------------------------------------------- launch
extern "C" void kernel_launch(void* const* d_in, const int* in_sizes, int n_in,
                              void* d_out, int out_size) {
    const float* node  = (const float*)d_in[0];
    const float* eattr = (const float*)d_in[1];
    const float* W     = (const float*)d_in[2];
    const float* b     = (const float*)d_in[3];
    const float* gw    = (const float*)d_in[4];
    const float* gb    = (const float*)d_in[5];
    const float* ms    = (const float*)d_in[6];
    const void*  ei    = d_in[7];
    const void*  batch = d_in[8];
    float* out = (float*)d_out;

    cudaFuncSetAttribute(k_gemm, cudaFuncAttributeMaxDynamicSharedMemorySize, SMEM_BYTES);

    k_init<<<(N_NODES + 255) / 256, 256>>>();
    k_convert<<<(N_EDGES + 255) / 256, 256>>>(ei, batch, eattr);
    k_fill<<<(N_EDGES + 255) / 256, 256>>>(eattr);
    {
        dim3 grid(DIM / 128, (N_NODES + 127) / 128);   // (4, 391)
        k_gemm<<<grid, 256, SMEM_BYTES>>>(node, W);
    }
    k_gather<<<(N_NODES + GW - 1) / GW, 256>>>(node, b);   // 6250 blocks
    k_final<<<(N_NODES * (DIM / 4) + 255) / 256, 256>>>(gw, gb, ms, out);
}

// round 15
// speedup vs baseline: 1.4357x; 1.0163x over previous
#include <cuda_runtime.h>
#include <cstdint>

#define N_NODES 50000
#define N_EDGES 160000
#define DIM     512
#define N_GRAPHS 64
#define EPSV    1e-5f

// GEMM tiling: BM=128, BN=128, BK=32, 3-stage cp.async, 8 warps, warp tile 64x32, 2 CTAs/SM
#define AS_STR 36
#define BS_STR 136
#define AS_ELE (128 * AS_STR)
#define BS_ELE (32 * BS_STR)
#define NSTAGE 3
#define SMEM_BYTES (NSTAGE * (AS_ELE + BS_ELE) * 4)   // 107520 B

// gather: padded CSR (32 slots/dst), full row per warp
#define SLOTS 32
#define GW 8                            // warps (=nodes) per gather block

struct Edge { int src; float w; };      // packed 8B CSR entry

// ---- scratch (static __device__: allocation-free) ----
__device__ float g_xw [(size_t)N_NODES * DIM];
__device__ float g_acc[(size_t)N_NODES * DIM];
__device__ float g_deg[N_NODES];
__device__ int   g_slot[N_NODES];
__device__ Edge  g_csr[(size_t)N_NODES * SLOTS];
__device__ float g_sum[N_GRAPHS * DIM];
__device__ float g_sq [N_GRAPHS * DIM];
__device__ float g_cnt[N_GRAPHS];
__device__ int   g_batch [N_NODES];

// ---------------------------------------------------------------- init
__global__ void k_init() {
    int i = blockIdx.x * blockDim.x + threadIdx.x;
    if (i < N_NODES) { g_deg[i] = 1.0f; g_slot[i] = 0; }
    if (i < N_GRAPHS * DIM) { g_sum[i] = 0.f; g_sq[i] = 0.f; }
    if (i < N_GRAPHS) g_cnt[i] = 0.f;
}

// ---------------------------------------------------------------- convert + degree + CSR fill (fused)
// CSR stores (src, w); coef is computed in the gather once degrees are final.
__global__ void k_convert(const void* __restrict__ ei, const void* __restrict__ batch,
                          const float* __restrict__ w) {
    __shared__ int s64;
    const int tid = threadIdx.x;
    if (tid == 0) {
        const long long* q = (const long long*)ei;
        int ok = 1;
#pragma unroll
        for (int i = 0; i < 8; i++) { long long v = q[i]; if (v < 0 || v >= N_NODES) ok = 0; }
        s64 = ok;
    }
    __syncthreads();
    const int is64 = s64;
    const int e = blockIdx.x * blockDim.x + tid;
    if (e < N_EDGES) {
        int r, c;
        if (is64) { r = (int)((const long long*)ei)[e]; c = (int)((const long long*)ei)[N_EDGES + e]; }
        else      { r = ((const int*)ei)[e];            c = ((const int*)ei)[N_EDGES + e]; }
        r = min(max(r, 0), N_NODES - 1);
        c = min(max(c, 0), N_NODES - 1);
        const float we = w[e];
        atomicAdd(&g_deg[c], we);
        const int slot = atomicAdd(&g_slot[c], 1);
        if (slot < SLOTS) {
            Edge ed; ed.src = r; ed.w = we;
            g_csr[(size_t)c * SLOTS + slot] = ed;
        }
    }
    if (e < N_NODES) {
        int bv = is64 ? (int)((const long long*)batch)[e] : ((const int*)batch)[e];
        g_batch[e] = min(max(bv, 0), N_GRAPHS - 1);
    }
}

// ---------------------------------------------------------------- helpers
__device__ __forceinline__ void cpasync16(uint32_t dst, const void* src) {
    asm volatile("cp.async.cg.shared.global [%0], [%1], 16;" :: "r"(dst), "l"(src));
}
#define CP_COMMIT()  asm volatile("cp.async.commit_group;" ::: "memory")
#define CP_WAIT(n)   asm volatile("cp.async.wait_group %0;" :: "n"(n) : "memory")
__device__ __forceinline__ uint32_t smem_u32(const void* p) {
    uint32_t a;
    asm("{ .reg .u64 t; cvta.to.shared.u64 t, %1; cvt.u32.u64 %0, t; }" : "=r"(a) : "l"(p));
    return a;
}
__device__ __forceinline__ void mma_tf32(float* d, const uint32_t* a, const uint32_t* b) {
    asm volatile(
        "mma.sync.aligned.m16n8k8.row.col.f32.tf32.tf32.f32 "
        "{%0,%1,%2,%3},{%4,%5,%6,%7},{%8,%9},{%0,%1,%2,%3};\n"
        : "+f"(d[0]), "+f"(d[1]), "+f"(d[2]), "+f"(d[3])
        : "r"(a[0]), "r"(a[1]), "r"(a[2]), "r"(a[3]), "r"(b[0]), "r"(b[1]));
}
__device__ __forceinline__ void red4(float* p, float4 v) {
    asm volatile("red.global.add.v4.f32 [%0], {%1,%2,%3,%4};"
                 :: "l"(p), "f"(v.x), "f"(v.y), "f"(v.z), "f"(v.w) : "memory");
}
__device__ __forceinline__ void acc4(float4& a, float4 v, float c) {
    a.x += v.x * c; a.y += v.y * c; a.z += v.z * c; a.w += v.w * c;
}

// ---------------------------------------------------------------- GEMM (epilogue writes g_xw only)
__global__ void __launch_bounds__(256, 2) k_gemm(
    const float* __restrict__ A,
    const float* __restrict__ B)
{
    extern __shared__ float smem[];
    const uint32_t sbase = smem_u32(smem);
    const int tid  = threadIdx.x;
    const int lane = tid & 31;
    const int warp = tid >> 5;
    const int wm = warp >> 2;   // 0..1
    const int wn = warp & 3;    // 0..3
    const int m0 = blockIdx.y * 128;
    const int n0 = blockIdx.x * 128;

    float acc[4][4][4];
#pragma unroll
    for (int i = 0; i < 4; i++)
#pragma unroll
        for (int j = 0; j < 4; j++)
#pragma unroll
            for (int c = 0; c < 4; c++) acc[i][j][c] = 0.f;

#define ISSUE(KT) do {                                                           \
        const int kk = (KT) * 32;                                                \
        const uint32_t sa = sbase + ((KT) % NSTAGE) * (AS_ELE * 4);              \
        const uint32_t sbb = sbase + (NSTAGE * AS_ELE + ((KT) % NSTAGE) * BS_ELE) * 4; \
        _Pragma("unroll")                                                        \
        for (int i = 0; i < 4; i++) {                                            \
            const int idx = tid + i * 256;                                       \
            const int row = idx >> 3, col = (idx & 7) * 4;                       \
            int gm = m0 + row;                                                   \
            if (gm >= N_NODES) gm = N_NODES - 1;                                 \
            cpasync16(sa + (uint32_t)(row * AS_STR + col) * 4,                   \
                      A + (size_t)gm * 512 + kk + col);                          \
        }                                                                        \
        _Pragma("unroll")                                                        \
        for (int i = 0; i < 4; i++) {                                            \
            const int idx = tid + i * 256;                                       \
            const int row = idx >> 5, col = (idx & 31) * 4;                      \
            cpasync16(sbb + (uint32_t)(row * BS_STR + col) * 4,                  \
                      B + (size_t)(kk + row) * 512 + n0 + col);                  \
        }                                                                        \
        CP_COMMIT();                                                             \
    } while (0)

    ISSUE(0);
    ISSUE(1);

#pragma unroll 1
    for (int kt = 0; kt < 16; kt++) {
        CP_WAIT(1);
        __syncthreads();
        if (kt + 2 < 16) ISSUE(kt + 2);

        const float* as = smem + (kt % NSTAGE) * AS_ELE;
        const float* bs = smem + NSTAGE * AS_ELE + (kt % NSTAGE) * BS_ELE;
#pragma unroll
        for (int ks = 0; ks < 4; ks++) {
            uint32_t af[4][4], bf[4][2];
            const int kk = ks * 8 + (lane & 3);
#pragma unroll
            for (int i = 0; i < 4; i++) {
                const int r = wm * 64 + i * 16 + (lane >> 2);
                af[i][0] = __float_as_uint(as[r * AS_STR + kk]);
                af[i][1] = __float_as_uint(as[(r + 8) * AS_STR + kk]);
                af[i][2] = __float_as_uint(as[r * AS_STR + kk + 4]);
                af[i][3] = __float_as_uint(as[(r + 8) * AS_STR + kk + 4]);
            }
#pragma unroll
            for (int j = 0; j < 4; j++) {
                const int c = wn * 32 + j * 8 + (lane >> 2);
                bf[j][0] = __float_as_uint(bs[kk * BS_STR + c]);
                bf[j][1] = __float_as_uint(bs[(kk + 4) * BS_STR + c]);
            }
#pragma unroll
            for (int i = 0; i < 4; i++)
#pragma unroll
                for (int j = 0; j < 4; j++)
                    mma_tf32(acc[i][j], af[i], bf[j]);
        }
    }

    // epilogue: write xw only
#pragma unroll
    for (int i = 0; i < 4; i++) {
        const int rbase = m0 + wm * 64 + i * 16 + (lane >> 2);
#pragma unroll
        for (int h = 0; h < 2; h++) {
            const int gm = rbase + h * 8;
            if (gm < N_NODES) {
#pragma unroll
                for (int j = 0; j < 4; j++) {
                    const int cb = n0 + wn * 32 + j * 8 + ((lane & 3) << 1);
                    *(float2*)(g_xw + (size_t)gm * 512 + cb) =
                        make_float2(acc[i][j][h * 2 + 0], acc[i][j][h * 2 + 1]);
                }
            }
        }
    }
#undef ISSUE
}

// ---------------------------------------------------------------- CSR gather: full row per warp
// coef computed in-flight from (src, w) + final degrees.  Streaming hints
// keep the 100MB g_xw gather set L2-resident.  Fused GraphNorm stats with
// per-warp-chunk parallel block reduction.
__global__ void __launch_bounds__(256) k_gather(const float* __restrict__ node,
                                                const float* __restrict__ bias) {
    __shared__ float s_sum[GW][DIM];
    __shared__ float s_sq [GW][DIM];
    __shared__ int   s_gid[GW];
    const int w = threadIdx.x >> 5;
    const int t = threadIdx.x & 31;
    const int n = blockIdx.x * GW + w;          // 6250*8 = 50000 exactly
    const int off = t * 4;

    float4 a[4];
#pragma unroll
    for (int q = 0; q < 4; q++) a[q] = make_float4(0.f, 0.f, 0.f, 0.f);
    int g = -1;
    if (n < N_NODES) {
        g = g_batch[n];
        const int cnt = min(g_slot[n], SLOTS);
        const float invdeg = 1.0f / g_deg[n];
        const float rs_n = rsqrtf(g_deg[n]);
        const size_t nb = (size_t)n * DIM + off;
#pragma unroll
        for (int q = 0; q < 4; q++) {
            const float4 xn = *(const float4*)(g_xw + nb + q * 128);
            const float4 nd = __ldcs((const float4*)(node + nb + q * 128));
            const float4 b4 = *(const float4*)(bias + off + q * 128);
            a[q].x = nd.x + b4.x + xn.x * invdeg;
            a[q].y = nd.y + b4.y + xn.y * invdeg;
            a[q].z = nd.z + b4.z + xn.z * invdeg;
            a[q].w = nd.w + b4.w + xn.w * invdeg;
        }

        const size_t base = (size_t)n * SLOTS;
        int i = 0;
        for (; i + 2 <= cnt; i += 2) {
            const Edge e0 = g_csr[base + i + 0];
            const Edge e1 = g_csr[base + i + 1];
            const float c0 = e0.w * rsqrtf(g_deg[e0.src]) * rs_n;
            const float c1 = e1.w * rsqrtf(g_deg[e1.src]) * rs_n;
            const size_t o0 = (size_t)e0.src * DIM + off;
            const size_t o1 = (size_t)e1.src * DIM + off;
#pragma unroll
            for (int q = 0; q < 4; q++) {
                acc4(a[q], *(const float4*)(g_xw + o0 + q * 128), c0);
                acc4(a[q], *(const float4*)(g_xw + o1 + q * 128), c1);
            }
        }
        if (i < cnt) {
            const Edge e0 = g_csr[base + i];
            const float c0 = e0.w * rsqrtf(g_deg[e0.src]) * rs_n;
            const size_t o0 = (size_t)e0.src * DIM + off;
#pragma unroll
            for (int q = 0; q < 4; q++)
                acc4(a[q], *(const float4*)(g_xw + o0 + q * 128), c0);
        }
#pragma unroll
        for (int q = 0; q < 4; q++)
            __stcs((float4*)(g_acc + nb + q * 128), a[q]);
        if (t == 0) atomicAdd(&g_cnt[g], 1.0f);
    }
    if (t == 0) s_gid[w] = g;
#pragma unroll
    for (int q = 0; q < 4; q++) {
        *(float4*)&s_sum[w][off + q * 128] = a[q];
        *(float4*)&s_sq [w][off + q * 128] =
            make_float4(a[q].x * a[q].x, a[q].y * a[q].y, a[q].z * a[q].z, a[q].w * a[q].w);
    }
    __syncthreads();

    const int g0 = s_gid[0];
    bool uni = true;
#pragma unroll
    for (int i = 1; i < GW; i++) {
        const int gi = s_gid[i];
        uni &= (gi == g0 || gi < 0);
    }
    if (uni) {
        // warp w reduces dim chunk [w*64, w*64+64): lanes 0-15 sum, 16-31 sq
        if (g0 >= 0) {
            const int half = t >> 4;            // 0: sum, 1: sq
            const int d = w * 64 + (t & 15) * 4;
            const float (*src)[DIM] = half ? s_sq : s_sum;
            float4 S = make_float4(0.f, 0.f, 0.f, 0.f);
#pragma unroll
            for (int i = 0; i < GW; i++) {
                const float4 p = *(const float4*)&src[i][d];
                S.x += p.x; S.y += p.y; S.z += p.z; S.w += p.w;
            }
            red4((half ? g_sq : g_sum) + g0 * DIM + d, S);
        }
    } else {
        // rare mixed-graph block: each warp REDs its own node's values
        if (g >= 0) {
#pragma unroll
            for (int q = 0; q < 4; q++) {
                const int d = q * 128 + off;
                red4(&g_sum[g * DIM + d], a[q]);
                red4(&g_sq [g * DIM + d],
                     make_float4(a[q].x * a[q].x, a[q].y * a[q].y,
                                 a[q].z * a[q].z, a[q].w * a[q].w));
            }
        }
    }
}

// ---------------------------------------------------------------- finalize: normalize + relu
// 32 threads per node, 4 x float4 per thread (MLP=4 on the 200MB stream)
__global__ __launch_bounds__(256) void k_final(const float* __restrict__ gw,
                                               const float* __restrict__ gb,
                                               const float* __restrict__ ms,
                                               float* __restrict__ out) {
    const int idx = blockIdx.x * blockDim.x + threadIdx.x;
    if (idx >= N_NODES * 32) return;
    const int n = idx >> 5;
    const int t = idx & 31;
    const int g = g_batch[n];
    const float ic = 1.f / fmaxf(g_cnt[g], 1.f);
    const size_t nb = (size_t)n * DIM + t * 4;
#pragma unroll
    for (int q = 0; q < 4; q++) {
        const int dc = t * 4 + q * 128;
        const float4 x  = __ldcs((const float4*)(g_acc + nb + q * 128));
        const float4 sm = *(const float4*)(g_sum + g * DIM + dc);
        const float4 sq = *(const float4*)(g_sq  + g * DIM + dc);
        const float4 w4 = *(const float4*)(gw + dc);
        const float4 b4 = *(const float4*)(gb + dc);
        const float4 m4 = *(const float4*)(ms + dc);
        float4 o;
        {
            const float m = sm.x * ic, c = m * m4.x;
            const float var = sq.x * ic - 2.f * c * m + c * c;
            o.x = fmaxf(w4.x * (x.x - c) * rsqrtf(var + EPSV) + b4.x, 0.f);
        }
        {
            const float m = sm.y * ic, c = m * m4.y;
            const float var = sq.y * ic - 2.f * c * m + c * c;
            o.y = fmaxf(w4.y * (x.y - c) * rsqrtf(var + EPSV) + b4.y, 0.f);
        }
        {
            const float m = sm.z * ic, c = m * m4.z;
            const float var = sq.z * ic - 2.f * c * m + c * c;
            o.z = fmaxf(w4.z * (x.z - c) * rsqrtf(var + EPSV) + b4.z, 0.f);
        }
        {
            const float m = sm.w * ic, c = m * m4.w;
            const float var = sq.w * ic - 2.f * c * m + c * c;
            o.w = fmaxf(w4.w * (x.w - c) * rsqrtf(var + EPSV) + b4.w, 0.f);
        }
        __stcs((float4*)(out + nb + q * 128), o);
    }
}

// ---------------------------------------------------------------- launch
extern "C" void kernel_launch(void* const* d_in, const int* in_sizes, int n_in,
                              void* d_out, int out_size) {
    const float* node  = (const float*)d_in[0];
    const float* eattr = (const float*)d_in[1];
    const float* W     = (const float*)d_in[2];
    const float* b     = (const float*)d_in[3];
    const float* gw    = (const float*)d_in[4];
    const float* gb    = (const float*)d_in[5];
    const float* ms    = (const float*)d_in[6];
    const void*  ei    = d_in[7];
    const void*  batch = d_in[8];
    float* out = (float*)d_out;

    cudaFuncSetAttribute(k_gemm, cudaFuncAttributeMaxDynamicSharedMemorySize, SMEM_BYTES);

    k_init<<<(N_NODES + 255) / 256, 256>>>();
    k_convert<<<(N_EDGES + 255) / 256, 256>>>(ei, batch, eattr);
    {
        dim3 grid(DIM / 128, (N_NODES + 127) / 128);   // (4, 391)
        k_gemm<<<grid, 256, SMEM_BYTES>>>(node, W);
    }
    k_gather<<<(N_NODES + GW - 1) / GW, 256>>>(node, b);   // 6250 blocks
    k_final<<<(N_NODES * 32 + 255) / 256, 256>>>(gw, gb, ms, out);
}

// round 16
// speedup vs baseline: 1.4778x; 1.0293x over previous
#include <cuda_runtime.h>
#include <cuda_fp16.h>
#include <cstdint>

#define N_NODES 50000
#define N_EDGES 160000
#define DIM     512
#define N_GRAPHS 64
#define EPSV    1e-5f

// GEMM tiling: BM=128, BN=128, BK=32, 3-stage cp.async, 8 warps, warp tile 64x32, 2 CTAs/SM
#define AS_STR 36
#define BS_STR 136
#define AS_ELE (128 * AS_STR)
#define BS_ELE (32 * BS_STR)
#define NSTAGE 3
#define SMEM_BYTES (NSTAGE * (AS_ELE + BS_ELE) * 4)   // 107520 B

// gather: padded CSR (32 slots/dst), full row per warp
#define SLOTS 32
#define GW 8

struct Edge { int src; float w; };

// ---- scratch (static __device__: allocation-free) ----
__device__ __half g_xw [(size_t)N_NODES * DIM];      // x @ W in fp16 (50MB: L2-resident)
__device__ float  g_acc[(size_t)N_NODES * DIM];
__device__ float  g_deg[N_NODES];
__device__ int    g_slot[N_NODES];
__device__ Edge   g_csr[(size_t)N_NODES * SLOTS];
__device__ float  g_sum[N_GRAPHS * DIM];
__device__ float  g_sq [N_GRAPHS * DIM];
__device__ float  g_cnt[N_GRAPHS];
__device__ int    g_batch [N_NODES];

// ---------------------------------------------------------------- init
__global__ void k_init() {
    int i = blockIdx.x * blockDim.x + threadIdx.x;
    if (i < N_NODES) { g_deg[i] = 1.0f; g_slot[i] = 0; }
    if (i < N_GRAPHS * DIM) { g_sum[i] = 0.f; g_sq[i] = 0.f; }
    if (i < N_GRAPHS) g_cnt[i] = 0.f;
}

// ---------------------------------------------------------------- convert + degree + CSR fill (fused)
__global__ void k_convert(const void* __restrict__ ei, const void* __restrict__ batch,
                          const float* __restrict__ w) {
    __shared__ int s64;
    const int tid = threadIdx.x;
    if (tid == 0) {
        const long long* q = (const long long*)ei;
        int ok = 1;
#pragma unroll
        for (int i = 0; i < 8; i++) { long long v = q[i]; if (v < 0 || v >= N_NODES) ok = 0; }
        s64 = ok;
    }
    __syncthreads();
    const int is64 = s64;
    const int e = blockIdx.x * blockDim.x + tid;
    if (e < N_EDGES) {
        int r, c;
        if (is64) { r = (int)((const long long*)ei)[e]; c = (int)((const long long*)ei)[N_EDGES + e]; }
        else      { r = ((const int*)ei)[e];            c = ((const int*)ei)[N_EDGES + e]; }
        r = min(max(r, 0), N_NODES - 1);
        c = min(max(c, 0), N_NODES - 1);
        const float we = w[e];
        atomicAdd(&g_deg[c], we);
        const int slot = atomicAdd(&g_slot[c], 1);
        if (slot < SLOTS) {
            Edge ed; ed.src = r; ed.w = we;
            g_csr[(size_t)c * SLOTS + slot] = ed;
        }
    }
    if (e < N_NODES) {
        int bv = is64 ? (int)((const long long*)batch)[e] : ((const int*)batch)[e];
        g_batch[e] = min(max(bv, 0), N_GRAPHS - 1);
    }
}

// ---------------------------------------------------------------- helpers
__device__ __forceinline__ void cpasync16(uint32_t dst, const void* src) {
    asm volatile("cp.async.cg.shared.global [%0], [%1], 16;" :: "r"(dst), "l"(src));
}
#define CP_COMMIT()  asm volatile("cp.async.commit_group;" ::: "memory")
#define CP_WAIT(n)   asm volatile("cp.async.wait_group %0;" :: "n"(n) : "memory")
__device__ __forceinline__ uint32_t smem_u32(const void* p) {
    uint32_t a;
    asm("{ .reg .u64 t; cvta.to.shared.u64 t, %1; cvt.u32.u64 %0, t; }" : "=r"(a) : "l"(p));
    return a;
}
__device__ __forceinline__ void mma_tf32(float* d, const uint32_t* a, const uint32_t* b) {
    asm volatile(
        "mma.sync.aligned.m16n8k8.row.col.f32.tf32.tf32.f32 "
        "{%0,%1,%2,%3},{%4,%5,%6,%7},{%8,%9},{%0,%1,%2,%3};\n"
        : "+f"(d[0]), "+f"(d[1]), "+f"(d[2]), "+f"(d[3])
        : "r"(a[0]), "r"(a[1]), "r"(a[2]), "r"(a[3]), "r"(b[0]), "r"(b[1]));
}
__device__ __forceinline__ void red4(float* p, float4 v) {
    asm volatile("red.global.add.v4.f32 [%0], {%1,%2,%3,%4};"
                 :: "l"(p), "f"(v.x), "f"(v.y), "f"(v.z), "f"(v.w) : "memory");
}
// accumulate 4 halves (as uint2) scaled by c
__device__ __forceinline__ void acc4h(float4& a, uint2 u, float c) {
    const float2 lo = __half22float2(*(const __half2*)&u.x);
    const float2 hi = __half22float2(*(const __half2*)&u.y);
    a.x += lo.x * c; a.y += lo.y * c; a.z += hi.x * c; a.w += hi.y * c;
}

// ---------------------------------------------------------------- GEMM (epilogue writes fp16 g_xw)
__global__ void __launch_bounds__(256, 2) k_gemm(
    const float* __restrict__ A,
    const float* __restrict__ B)
{
    extern __shared__ float smem[];
    const uint32_t sbase = smem_u32(smem);
    const int tid  = threadIdx.x;
    const int lane = tid & 31;
    const int warp = tid >> 5;
    const int wm = warp >> 2;
    const int wn = warp & 3;
    const int m0 = blockIdx.y * 128;
    const int n0 = blockIdx.x * 128;

    float acc[4][4][4];
#pragma unroll
    for (int i = 0; i < 4; i++)
#pragma unroll
        for (int j = 0; j < 4; j++)
#pragma unroll
            for (int c = 0; c < 4; c++) acc[i][j][c] = 0.f;

#define ISSUE(KT) do {                                                           \
        const int kk = (KT) * 32;                                                \
        const uint32_t sa = sbase + ((KT) % NSTAGE) * (AS_ELE * 4);              \
        const uint32_t sbb = sbase + (NSTAGE * AS_ELE + ((KT) % NSTAGE) * BS_ELE) * 4; \
        _Pragma("unroll")                                                        \
        for (int i = 0; i < 4; i++) {                                            \
            const int idx = tid + i * 256;                                       \
            const int row = idx >> 3, col = (idx & 7) * 4;                       \
            int gm = m0 + row;                                                   \
            if (gm >= N_NODES) gm = N_NODES - 1;                                 \
            cpasync16(sa + (uint32_t)(row * AS_STR + col) * 4,                   \
                      A + (size_t)gm * 512 + kk + col);                          \
        }                                                                        \
        _Pragma("unroll")                                                        \
        for (int i = 0; i < 4; i++) {                                            \
            const int idx = tid + i * 256;                                       \
            const int row = idx >> 5, col = (idx & 31) * 4;                      \
            cpasync16(sbb + (uint32_t)(row * BS_STR + col) * 4,                  \
                      B + (size_t)(kk + row) * 512 + n0 + col);                  \
        }                                                                        \
        CP_COMMIT();                                                             \
    } while (0)

    ISSUE(0);
    ISSUE(1);

#pragma unroll 1
    for (int kt = 0; kt < 16; kt++) {
        CP_WAIT(1);
        __syncthreads();
        if (kt + 2 < 16) ISSUE(kt + 2);

        const float* as = smem + (kt % NSTAGE) * AS_ELE;
        const float* bs = smem + NSTAGE * AS_ELE + (kt % NSTAGE) * BS_ELE;
#pragma unroll
        for (int ks = 0; ks < 4; ks++) {
            uint32_t af[4][4], bf[4][2];
            const int kk = ks * 8 + (lane & 3);
#pragma unroll
            for (int i = 0; i < 4; i++) {
                const int r = wm * 64 + i * 16 + (lane >> 2);
                af[i][0] = __float_as_uint(as[r * AS_STR + kk]);
                af[i][1] = __float_as_uint(as[(r + 8) * AS_STR + kk]);
                af[i][2] = __float_as_uint(as[r * AS_STR + kk + 4]);
                af[i][3] = __float_as_uint(as[(r + 8) * AS_STR + kk + 4]);
            }
#pragma unroll
            for (int j = 0; j < 4; j++) {
                const int c = wn * 32 + j * 8 + (lane >> 2);
                bf[j][0] = __float_as_uint(bs[kk * BS_STR + c]);
                bf[j][1] = __float_as_uint(bs[(kk + 4) * BS_STR + c]);
            }
#pragma unroll
            for (int i = 0; i < 4; i++)
#pragma unroll
                for (int j = 0; j < 4; j++)
                    mma_tf32(acc[i][j], af[i], bf[j]);
        }
    }

    // epilogue: write xw (fp16)
#pragma unroll
    for (int i = 0; i < 4; i++) {
        const int rbase = m0 + wm * 64 + i * 16 + (lane >> 2);
#pragma unroll
        for (int h = 0; h < 2; h++) {
            const int gm = rbase + h * 8;
            if (gm < N_NODES) {
#pragma unroll
                for (int j = 0; j < 4; j++) {
                    const int cb = n0 + wn * 32 + j * 8 + ((lane & 3) << 1);
                    const __half2 hv = __floats2half2_rn(acc[i][j][h * 2 + 0],
                                                         acc[i][j][h * 2 + 1]);
                    *(__half2*)(g_xw + (size_t)gm * 512 + cb) = hv;
                }
            }
        }
    }
#undef ISSUE
}

// ---------------------------------------------------------------- CSR gather: full row per warp
// fp16 xw (50MB, L2-resident) + in-flight coef + fused GraphNorm stats.
__global__ void __launch_bounds__(256) k_gather(const float* __restrict__ node,
                                                const float* __restrict__ bias) {
    __shared__ float s_sum[GW][DIM];
    __shared__ float s_sq [GW][DIM];
    __shared__ int   s_gid[GW];
    const int w = threadIdx.x >> 5;
    const int t = threadIdx.x & 31;
    const int n = blockIdx.x * GW + w;
    const int off = t * 4;

    float4 a[4];
#pragma unroll
    for (int q = 0; q < 4; q++) a[q] = make_float4(0.f, 0.f, 0.f, 0.f);
    int g = -1;
    if (n < N_NODES) {
        g = g_batch[n];
        const int cnt = min(g_slot[n], SLOTS);
        const float invdeg = 1.0f / g_deg[n];
        const float rs_n = rsqrtf(g_deg[n]);
        const size_t nb = (size_t)n * DIM + off;
#pragma unroll
        for (int q = 0; q < 4; q++) {
            const float4 nd = __ldcs((const float4*)(node + nb + q * 128));
            const float4 b4 = *(const float4*)(bias + off + q * 128);
            a[q].x = nd.x + b4.x;
            a[q].y = nd.y + b4.y;
            a[q].z = nd.z + b4.z;
            a[q].w = nd.w + b4.w;
            const uint2 u = *(const uint2*)(g_xw + nb + q * 128);
            acc4h(a[q], u, invdeg);
        }

        const size_t base = (size_t)n * SLOTS;
        int i = 0;
        for (; i + 2 <= cnt; i += 2) {
            const Edge e0 = g_csr[base + i + 0];
            const Edge e1 = g_csr[base + i + 1];
            const float c0 = e0.w * rsqrtf(g_deg[e0.src]) * rs_n;
            const float c1 = e1.w * rsqrtf(g_deg[e1.src]) * rs_n;
            const size_t o0 = (size_t)e0.src * DIM + off;
            const size_t o1 = (size_t)e1.src * DIM + off;
#pragma unroll
            for (int q = 0; q < 4; q++) {
                acc4h(a[q], *(const uint2*)(g_xw + o0 + q * 128), c0);
                acc4h(a[q], *(const uint2*)(g_xw + o1 + q * 128), c1);
            }
        }
        if (i < cnt) {
            const Edge e0 = g_csr[base + i];
            const float c0 = e0.w * rsqrtf(g_deg[e0.src]) * rs_n;
            const size_t o0 = (size_t)e0.src * DIM + off;
#pragma unroll
            for (int q = 0; q < 4; q++)
                acc4h(a[q], *(const uint2*)(g_xw + o0 + q * 128), c0);
        }
#pragma unroll
        for (int q = 0; q < 4; q++)
            __stcs((float4*)(g_acc + nb + q * 128), a[q]);
        if (t == 0) atomicAdd(&g_cnt[g], 1.0f);
    }
    if (t == 0) s_gid[w] = g;
#pragma unroll
    for (int q = 0; q < 4; q++) {
        *(float4*)&s_sum[w][off + q * 128] = a[q];
        *(float4*)&s_sq [w][off + q * 128] =
            make_float4(a[q].x * a[q].x, a[q].y * a[q].y, a[q].z * a[q].z, a[q].w * a[q].w);
    }
    __syncthreads();

    const int g0 = s_gid[0];
    bool uni = true;
#pragma unroll
    for (int i = 1; i < GW; i++) {
        const int gi = s_gid[i];
        uni &= (gi == g0 || gi < 0);
    }
    if (uni) {
        if (g0 >= 0) {
            const int half = t >> 4;
            const int d = w * 64 + (t & 15) * 4;
            const float (*src)[DIM] = half ? s_sq : s_sum;
            float4 S = make_float4(0.f, 0.f, 0.f, 0.f);
#pragma unroll
            for (int i = 0; i < GW; i++) {
                const float4 p = *(const float4*)&src[i][d];
                S.x += p.x; S.y += p.y; S.z += p.z; S.w += p.w;
            }
            red4((half ? g_sq : g_sum) + g0 * DIM + d, S);
        }
    } else {
        if (g >= 0) {
#pragma unroll
            for (int q = 0; q < 4; q++) {
                const int d = q * 128 + off;
                red4(&g_sum[g * DIM + d], a[q]);
                red4(&g_sq [g * DIM + d],
                     make_float4(a[q].x * a[q].x, a[q].y * a[q].y,
                                 a[q].z * a[q].z, a[q].w * a[q].w));
            }
        }
    }
}

// ---------------------------------------------------------------- finalize: normalize + relu
__global__ __launch_bounds__(256) void k_final(const float* __restrict__ gw,
                                               const float* __restrict__ gb,
                                               const float* __restrict__ ms,
                                               float* __restrict__ out) {
    const int idx = blockIdx.x * blockDim.x + threadIdx.x;
    if (idx >= N_NODES * 32) return;
    const int n = idx >> 5;
    const int t = idx & 31;
    const int g = g_batch[n];
    const float ic = 1.f / fmaxf(g_cnt[g], 1.f);
    const size_t nb = (size_t)n * DIM + t * 4;
#pragma unroll
    for (int q = 0; q < 4; q++) {
        const int dc = t * 4 + q * 128;
        const float4 x  = __ldcs((const float4*)(g_acc + nb + q * 128));
        const float4 sm = *(const float4*)(g_sum + g * DIM + dc);
        const float4 sq = *(const float4*)(g_sq  + g * DIM + dc);
        const float4 w4 = *(const float4*)(gw + dc);
        const float4 b4 = *(const float4*)(gb + dc);
        const float4 m4 = *(const float4*)(ms + dc);
        float4 o;
        {
            const float m = sm.x * ic, c = m * m4.x;
            const float var = sq.x * ic - 2.f * c * m + c * c;
            o.x = fmaxf(w4.x * (x.x - c) * rsqrtf(var + EPSV) + b4.x, 0.f);
        }
        {
            const float m = sm.y * ic, c = m * m4.y;
            const float var = sq.y * ic - 2.f * c * m + c * c;
            o.y = fmaxf(w4.y * (x.y - c) * rsqrtf(var + EPSV) + b4.y, 0.f);
        }
        {
            const float m = sm.z * ic, c = m * m4.z;
            const float var = sq.z * ic - 2.f * c * m + c * c;
            o.z = fmaxf(w4.z * (x.z - c) * rsqrtf(var + EPSV) + b4.z, 0.f);
        }
        {
            const float m = sm.w * ic, c = m * m4.w;
            const float var = sq.w * ic - 2.f * c * m + c * c;
            o.w = fmaxf(w4.w * (x.w - c) * rsqrtf(var + EPSV) + b4.w, 0.f);
        }
        __stcs((float4*)(out + nb + q * 128), o);
    }
}

// ---------------------------------------------------------------- launch
extern "C" void kernel_launch(void* const* d_in, const int* in_sizes, int n_in,
                              void* d_out, int out_size) {
    const float* node  = (const float*)d_in[0];
    const float* eattr = (const float*)d_in[1];
    const float* W     = (const float*)d_in[2];
    const float* b     = (const float*)d_in[3];
    const float* gw    = (const float*)d_in[4];
    const float* gb    = (const float*)d_in[5];
    const float* ms    = (const float*)d_in[6];
    const void*  ei    = d_in[7];
    const void*  batch = d_in[8];
    float* out = (float*)d_out;

    cudaFuncSetAttribute(k_gemm, cudaFuncAttributeMaxDynamicSharedMemorySize, SMEM_BYTES);

    k_init<<<(N_NODES + 255) / 256, 256>>>();
    k_convert<<<(N_EDGES + 255) / 256, 256>>>(ei, batch, eattr);
    {
        dim3 grid(DIM / 128, (N_NODES + 127) / 128);   // (4, 391)
        k_gemm<<<grid, 256, SMEM_BYTES>>>(node, W);
    }
    k_gather<<<(N_NODES + GW - 1) / GW, 256>>>(node, b);   // 6250 blocks
    k_final<<<(N_NODES * 32 + 255) / 256, 256>>>(gw, gb, ms, out);
}